// round 1
// baseline (speedup 1.0000x reference)
#include <cuda_runtime.h>
#include <math.h>

// Problem constants (fixed shapes from reference)
#define B_   4
#define S_   2048
#define IN_  512
#define H_   1024
#define M_   (B_ * S_)   // 8192 rows flattened (b, s)
#define AW   33          // 2*atten_size + 1

// Scratch (device globals: allocation-free per harness rules)
__device__ float g_h[(size_t)M_ * H_];
__device__ float g_q[(size_t)M_ * H_];

// ============================================================================
// SGEMM: C[M,N] = A[M,K] @ B[K,N]  (+ bias, relu optional)
// 128x128 block tile, BK=16, 256 threads, 8x8 per-thread micro tile.
// All dims divide tiles exactly (M=8192, N=1024, K=512/1024) -> no bounds checks.
// ============================================================================
#define BM 128
#define BN 128
#define BK 16
#define TM 8
#define TN 8

template <bool RELU_BIAS>
__global__ __launch_bounds__(256, 2)
void sgemm_kernel(const float* __restrict__ A, const float* __restrict__ B,
                  const float* __restrict__ bias, float* __restrict__ C,
                  int M, int N, int K)
{
    __shared__ float As[BK][BM];   // transposed A tile: As[k][m]
    __shared__ float Bs[BK][BN];

    const int tid = threadIdx.x;
    const int m0 = blockIdx.y * BM;
    const int n0 = blockIdx.x * BN;

    const int tx = tid % 16;   // 16 x 16 thread grid
    const int ty = tid / 16;

    float acc[TM][TN];
    #pragma unroll
    for (int i = 0; i < TM; i++)
        #pragma unroll
        for (int j = 0; j < TN; j++)
            acc[i][j] = 0.f;

    // Load indexing: A tile 128x16 -> 512 float4 (2 per thread)
    const int arow = tid / 4;          // 0..63
    const int acol = (tid % 4) * 4;    // 0,4,8,12
    // B tile 16x128 -> 512 float4 (2 per thread)
    const int brow = tid / 32;         // 0..7
    const int bcol = (tid % 32) * 4;

    for (int k0 = 0; k0 < K; k0 += BK) {
        #pragma unroll
        for (int r = 0; r < 2; r++) {
            const int row = arow + r * 64;
            float4 v = *(const float4*)(A + (size_t)(m0 + row) * K + k0 + acol);
            As[acol + 0][row] = v.x;
            As[acol + 1][row] = v.y;
            As[acol + 2][row] = v.z;
            As[acol + 3][row] = v.w;
        }
        #pragma unroll
        for (int r = 0; r < 2; r++) {
            const int row = brow + r * 8;
            *(float4*)(&Bs[row][bcol]) =
                *(const float4*)(B + (size_t)(k0 + row) * N + n0 + bcol);
        }
        __syncthreads();

        #pragma unroll
        for (int k = 0; k < BK; k++) {
            float a[TM], bb[TN];
            #pragma unroll
            for (int i = 0; i < TM; i += 4)
                *(float4*)&a[i] = *(float4*)&As[k][ty * TM + i];
            #pragma unroll
            for (int j = 0; j < TN; j += 4)
                *(float4*)&bb[j] = *(float4*)&Bs[k][tx * TN + j];
            #pragma unroll
            for (int i = 0; i < TM; i++)
                #pragma unroll
                for (int j = 0; j < TN; j++)
                    acc[i][j] += a[i] * bb[j];
        }
        __syncthreads();
    }

    #pragma unroll
    for (int i = 0; i < TM; i++) {
        const int row = m0 + ty * TM + i;
        #pragma unroll
        for (int j = 0; j < TN; j += 4) {
            const int col = n0 + tx * TN + j;
            float4 v;
            v.x = acc[i][j + 0];
            v.y = acc[i][j + 1];
            v.z = acc[i][j + 2];
            v.w = acc[i][j + 3];
            if (RELU_BIAS) {
                v.x = fmaxf(v.x + bias[col + 0], 0.f);
                v.y = fmaxf(v.y + bias[col + 1], 0.f);
                v.z = fmaxf(v.z + bias[col + 2], 0.f);
                v.w = fmaxf(v.w + bias[col + 3], 0.f);
            }
            *(float4*)(C + (size_t)row * N + col) = v;
        }
    }
}

// ============================================================================
// Local windowed attention.
// Per block: one batch, TS=16 consecutive sequence positions.
// neighbor(s, w) = global row (s0+s) + 16 - w, w in [0, 33); out-of-range rows
// are ZERO (reference pads with zeros and does NOT mask softmax).
// scores[s][w] = (q[s] . h[nbr]) / 32;  p = softmax_w;  out[s] = sum_w p*h[nbr]
// ============================================================================
#define TS 16
#define KC 128
#define HR (TS + 32)   // 48 neighborhood rows
#define HP 129         // hs pitch (odd -> conflict-free strided row access)

__global__ __launch_bounds__(256)
void atten_kernel(const float* __restrict__ h, const float* __restrict__ q,
                  float* __restrict__ out)
{
    __shared__ float qs[TS][KC];        // 8 KB
    __shared__ float hs[HR][HP];        // ~24.2 KB
    __shared__ float sc[TS][AW + 3];    // scores / probs

    const int tid = threadIdx.x;
    const int b = blockIdx.y;
    const int s0 = blockIdx.x * TS;

    const float* hB = h + (size_t)b * S_ * H_;
    const float* qB = q + (size_t)b * S_ * H_;
    float*       oB = out + (size_t)b * S_ * H_;

    // Each thread owns up to 3 (s, w) score pairs (16*33 = 528 pairs).
    int ps[3], pr[3];
    bool pv[3];
    float acc[3] = {0.f, 0.f, 0.f};
    #pragma unroll
    for (int u = 0; u < 3; u++) {
        const int p = tid + u * 256;
        pv[u] = (p < TS * AW);
        const int s = pv[u] ? (p / AW) : 0;
        const int w = pv[u] ? (p % AW) : 0;
        ps[u] = s;
        pr[u] = s + 32 - w;   // local hs row
    }

    // ---------------- Phase A: scores ----------------
    for (int kc = 0; kc < H_; kc += KC) {
        // q tile (float4, pitch 128 keeps alignment)
        for (int i = tid; i < TS * KC / 4; i += 256) {
            const int row = i / (KC / 4);
            const int col = (i % (KC / 4)) * 4;
            *(float4*)&qs[row][col] =
                *(const float4*)(qB + (size_t)(s0 + row) * H_ + kc + col);
        }
        // h neighborhood (scalar: pitch 129; zero-fill out-of-range rows)
        for (int i = tid; i < HR * KC; i += 256) {
            const int r = i / KC;
            const int c = i % KC;
            const int g = s0 - 16 + r;
            hs[r][c] = (g >= 0 && g < S_) ? hB[(size_t)g * H_ + kc + c] : 0.f;
        }
        __syncthreads();

        #pragma unroll
        for (int u = 0; u < 3; u++) {
            if (pv[u]) {
                const float* qrow = qs[ps[u]];
                const float* hrow = hs[pr[u]];
                float sum = acc[u];
                #pragma unroll 8
                for (int k = 0; k < KC; k++)
                    sum += qrow[k] * hrow[k];
                acc[u] = sum;
            }
        }
        __syncthreads();
    }

    #pragma unroll
    for (int u = 0; u < 3; u++) {
        if (pv[u]) {
            const int p = tid + u * 256;
            sc[p / AW][p % AW] = acc[u] * 0.03125f;  // 1/sqrt(1024)
        }
    }
    __syncthreads();

    // ---------------- Phase B: softmax (one thread per s) ----------------
    if (tid < TS) {
        float m = -1e30f;
        for (int w = 0; w < AW; w++) m = fmaxf(m, sc[tid][w]);
        float sum = 0.f;
        for (int w = 0; w < AW; w++) {
            const float e = expf(sc[tid][w] - m);
            sc[tid][w] = e;
            sum += e;
        }
        const float inv = 1.f / sum;
        for (int w = 0; w < AW; w++) sc[tid][w] *= inv;
    }
    __syncthreads();

    // ---------------- Phase C: weighted sum ----------------
    for (int kc = 0; kc < H_; kc += KC) {
        for (int i = tid; i < HR * KC; i += 256) {
            const int r = i / KC;
            const int c = i % KC;
            const int g = s0 - 16 + r;
            hs[r][c] = (g >= 0 && g < S_) ? hB[(size_t)g * H_ + kc + c] : 0.f;
        }
        __syncthreads();

        for (int o = tid; o < TS * KC; o += 256) {
            const int s = o / KC;
            const int k = o % KC;
            float sum = 0.f;
            #pragma unroll
            for (int w = 0; w < AW; w++)
                sum += sc[s][w] * hs[s + 32 - w][k];
            oB[(size_t)(s0 + s) * H_ + kc + k] = sum;
        }
        __syncthreads();
    }
}

// ============================================================================
// Launch
// ============================================================================
extern "C" void kernel_launch(void* const* d_in, const int* in_sizes, int n_in,
                              void* d_out, int out_size)
{
    const float* x  = (const float*)d_in[0];   // [4, 2048, 512]
    const float* W1 = (const float*)d_in[1];   // [512, 1024]
    const float* b1 = (const float*)d_in[2];   // [1024]
    const float* Wq = (const float*)d_in[3];   // [1024, 1024]
    float* out = (float*)d_out;                // [4, 2048, 1024]

    float* hp = nullptr;
    float* qp = nullptr;
    cudaGetSymbolAddress((void**)&hp, g_h);
    cudaGetSymbolAddress((void**)&qp, g_q);

    // GEMM1: h = relu(x @ W1 + b1)   [8192 x 512] @ [512 x 1024]
    {
        dim3 grid(H_ / BN, M_ / BM);
        sgemm_kernel<true><<<grid, 256>>>(x, W1, b1, hp, M_, H_, IN_);
    }
    // GEMM2: q = h @ Wq              [8192 x 1024] @ [1024 x 1024]
    {
        dim3 grid(H_ / BN, M_ / BM);
        sgemm_kernel<false><<<grid, 256>>>(hp, Wq, nullptr, qp, M_, H_, H_);
    }
    // Attention
    {
        dim3 grid(S_ / TS, B_);
        atten_kernel<<<grid, 256>>>(hp, qp, out);
    }
}

// round 4
// speedup vs baseline: 1.4401x; 1.4401x over previous
#include <cuda_runtime.h>
#include <cuda_fp16.h>
#include <math.h>
#include <stdint.h>

// ============================================================================
// Problem constants
// ============================================================================
#define B_   4
#define S_   2048
#define IN_  512
#define H_   1024
#define M_   (B_ * S_)   // 8192
#define AW   33          // 2*atten_size + 1

// ============================================================================
// Device global scratch (allocation-free per harness rules)
// ============================================================================
__device__ float g_h[(size_t)M_ * H_];
__device__ float g_q[(size_t)M_ * H_];

__device__ __half g_xhi[(size_t)M_ * IN_];
__device__ __half g_xlo[(size_t)M_ * IN_];
__device__ __half g_hhi[(size_t)M_ * H_];
__device__ __half g_hlo[(size_t)M_ * H_];
__device__ __half g_w1t_hi[(size_t)H_ * IN_];   // W1^T [1024,512]
__device__ __half g_w1t_lo[(size_t)H_ * IN_];
__device__ __half g_wqt_hi[(size_t)H_ * H_];    // Wq^T [1024,1024]
__device__ __half g_wqt_lo[(size_t)H_ * H_];

// ============================================================================
// PTX helpers (base sm_103 ISA only: cp.async, ldmatrix, mma.sync)
// ============================================================================
__device__ __forceinline__ uint32_t smem_u32(const void* p) {
    uint32_t a;
    asm("{ .reg .u64 t; cvta.to.shared.u64 t, %1; cvt.u32.u64 %0, t; }"
        : "=r"(a) : "l"(p));
    return a;
}

__device__ __forceinline__ void cp_async16(uint32_t dst, const void* src) {
    asm volatile("cp.async.cg.shared.global [%0], [%1], 16;"
                 :: "r"(dst), "l"(src));
}
#define CP_COMMIT() asm volatile("cp.async.commit_group;" ::: "memory")
#define CP_WAIT(n)  asm volatile("cp.async.wait_group %0;" :: "n"(n) : "memory")

__device__ __forceinline__ void ldsm_x4(uint32_t* r, uint32_t addr) {
    asm volatile("ldmatrix.sync.aligned.m8n8.x4.shared.b16 {%0,%1,%2,%3}, [%4];"
                 : "=r"(r[0]), "=r"(r[1]), "=r"(r[2]), "=r"(r[3]) : "r"(addr));
}

__device__ __forceinline__ void mma_f16(float* c, const uint32_t* a,
                                        uint32_t b0, uint32_t b1) {
    asm volatile(
        "mma.sync.aligned.m16n8k16.row.col.f32.f16.f16.f32 "
        "{%0,%1,%2,%3}, {%4,%5,%6,%7}, {%8,%9}, {%0,%1,%2,%3};"
        : "+f"(c[0]), "+f"(c[1]), "+f"(c[2]), "+f"(c[3])
        : "r"(a[0]), "r"(a[1]), "r"(a[2]), "r"(a[3]), "r"(b0), "r"(b1));
}

// ============================================================================
// Convert kernels: fp32 -> fp16 hi + fp16 lo (residual)
// ============================================================================
__global__ void split_kernel(const float* __restrict__ in,
                             __half* __restrict__ hi,
                             __half* __restrict__ lo, int n4) {
    int i = blockIdx.x * blockDim.x + threadIdx.x;
    if (i >= n4) return;
    float4 v = ((const float4*)in)[i];
    __half h0 = __float2half_rn(v.x), h1 = __float2half_rn(v.y);
    __half h2 = __float2half_rn(v.z), h3 = __float2half_rn(v.w);
    __half2 hp0 = __halves2half2(h0, h1), hp1 = __halves2half2(h2, h3);
    __half2 lp0 = __halves2half2(__float2half_rn(v.x - __half2float(h0)),
                                 __float2half_rn(v.y - __half2float(h1)));
    __half2 lp1 = __halves2half2(__float2half_rn(v.z - __half2float(h2)),
                                 __float2half_rn(v.w - __half2float(h3)));
    ((__half2*)hi)[i * 2 + 0] = hp0;
    ((__half2*)hi)[i * 2 + 1] = hp1;
    ((__half2*)lo)[i * 2 + 0] = lp0;
    ((__half2*)lo)[i * 2 + 1] = lp1;
}

// in [R, C] fp32 -> out^T [C, R] half hi/lo
__global__ void transpose_split_kernel(const float* __restrict__ in,
                                       __half* __restrict__ hiT,
                                       __half* __restrict__ loT,
                                       int R, int C) {
    __shared__ float t[32][33];
    const int c0 = blockIdx.x * 32, r0 = blockIdx.y * 32;
    const int tx = threadIdx.x, ty = threadIdx.y;   // 32 x 8
    #pragma unroll
    for (int j = 0; j < 32; j += 8)
        t[ty + j][tx] = in[(size_t)(r0 + ty + j) * C + c0 + tx];
    __syncthreads();
    #pragma unroll
    for (int j = 0; j < 32; j += 8) {
        float v = t[tx][ty + j];
        __half h = __float2half_rn(v);
        __half l = __float2half_rn(v - __half2float(h));
        size_t o = (size_t)(c0 + ty + j) * R + r0 + tx;
        hiT[o] = h;
        loT[o] = l;
    }
}

// ============================================================================
// HMMA split GEMM: C[M,N] = A[M,K] @ W[K,N], W given transposed [N,K].
// A, W split into fp16 hi/lo; C = AhiBhi + AhiBlo + AloBhi (fp32 accum).
// Block tile 128x128, BK=32, 8 warps (warp tile 64x32), 4-stage cp.async.
// SMEM row layout (128B): [hi k0..31 | lo k0..31], 16B groups XOR (row&7).
// B fragments come from NON-trans ldmatrix ([n][k] rows already give the
// required (n = lane>>2, k = (lane%4)*2) col-major-B fragment).
// ============================================================================
#define NST 4
#define STAGE_BYTES 32768   // A 16KB + B 16KB
#define GEMM_SMEM (NST * STAGE_BYTES)

template <bool G1>
__global__ __launch_bounds__(256, 1)
void hmma_gemm(const __half* __restrict__ Ahi, const __half* __restrict__ Alo,
               const __half* __restrict__ Bhi, const __half* __restrict__ Blo,
               const float* __restrict__ bias,
               float* __restrict__ outF,
               __half* __restrict__ outHi, __half* __restrict__ outLo,
               int K)
{
    extern __shared__ __align__(1024) char smem[];
    const uint32_t smBase = smem_u32(smem);

    const int tid  = threadIdx.x;
    const int wid  = tid >> 5;
    const int lane = tid & 31;
    const int m0 = blockIdx.y * 128;
    const int n0 = blockIdx.x * 128;
    const int nk = K / 32;

    const int wm = (wid & 1) * 64;    // warp m offset within block
    const int wn = (wid >> 1) * 32;   // warp n offset within block

    // --- loader mapping: each thread loads 4 A groups + 4 B groups/stage ---
    const int half_sel = tid & 1;         // 0 -> hi, 1 -> lo
    const int lrow = tid >> 1;            // 0..127
    const __half* srcA = (half_sel ? Alo : Ahi) + (size_t)(m0 + lrow) * K;
    const __half* srcB = (half_sel ? Blo : Bhi) + (size_t)(n0 + lrow) * K;
    uint32_t dstA[4], dstB[4];
    #pragma unroll
    for (int g = 0; g < 4; g++) {
        const int lg = half_sel * 4 + g;
        const int pg = (lg ^ (lrow & 7)) * 16;
        dstA[g] = smBase + lrow * 128 + pg;
        dstB[g] = smBase + 16384 + lrow * 128 + pg;
    }

    auto load_stage = [&](int c, int s) {
        const __half* sa = srcA + c * 32;
        const __half* sb = srcB + c * 32;
        const uint32_t so = s * STAGE_BYTES;
        #pragma unroll
        for (int g = 0; g < 4; g++) {
            cp_async16(dstA[g] + so, sa + g * 8);
            cp_async16(dstB[g] + so, sb + g * 8);
        }
    };

    float acc[4][4][4];
    #pragma unroll
    for (int mt = 0; mt < 4; mt++)
        #pragma unroll
        for (int nt = 0; nt < 4; nt++)
            #pragma unroll
            for (int j = 0; j < 4; j++)
                acc[mt][nt][j] = 0.f;

    // prologue: fill NST-1 stages
    #pragma unroll
    for (int c = 0; c < NST - 1; c++) {
        load_stage(c, c);
        CP_COMMIT();
    }

    // fragment addressing (constant per thread)
    const int arow_l = (lane & 15);          // A ldmatrix row within tile
    const int agrp_l = (lane >> 4);          // 0/1: which 16B group of k-step
    const int brow_l = (lane & 7) + ((lane >> 4) << 3);   // n row within 16
    const int bgrp_l = (lane >> 3) & 1;                   // k group within step

    for (int c = 0; c < nk; c++) {
        CP_WAIT(NST - 2);
        __syncthreads();
        // prefetch next stage
        if (c + NST - 1 < nk)
            load_stage(c + NST - 1, (c + NST - 1) % NST);
        CP_COMMIT();

        const uint32_t aB = smBase + (c % NST) * STAGE_BYTES;
        const uint32_t bB = aB + 16384;

        #pragma unroll
        for (int ks = 0; ks < 2; ks++) {
            uint32_t ahi[4][4], alo[4][4], bhi[2][4], blo[2][4];
            const int agH = ks * 2 + agrp_l;       // hi groups 0..3
            #pragma unroll
            for (int mt = 0; mt < 4; mt++) {
                const int row = wm + mt * 16 + arow_l;
                const uint32_t rb = aB + row * 128;
                ldsm_x4(ahi[mt], rb + ((agH ^ (row & 7)) * 16));
                ldsm_x4(alo[mt], rb + (((agH + 4) ^ (row & 7)) * 16));
            }
            const int bgH = ks * 2 + bgrp_l;
            #pragma unroll
            for (int np = 0; np < 2; np++) {
                const int row = wn + np * 16 + brow_l;
                const uint32_t rb = bB + row * 128;
                ldsm_x4(bhi[np], rb + ((bgH ^ (row & 7)) * 16));
                ldsm_x4(blo[np], rb + (((bgH + 4) ^ (row & 7)) * 16));
            }
            #pragma unroll
            for (int mt = 0; mt < 4; mt++) {
                #pragma unroll
                for (int nt = 0; nt < 4; nt++) {
                    const int np = nt >> 1, o = (nt & 1) * 2;
                    mma_f16(acc[mt][nt], ahi[mt], bhi[np][o], bhi[np][o + 1]);
                    mma_f16(acc[mt][nt], ahi[mt], blo[np][o], blo[np][o + 1]);
                    mma_f16(acc[mt][nt], alo[mt], bhi[np][o], bhi[np][o + 1]);
                }
            }
        }
        __syncthreads();
    }

    // ---------------- epilogue ----------------
    const int r0 = lane >> 2;            // 0..7
    const int c0 = (lane & 3) * 2;

    float2 bias2[4];
    if (G1) {
        #pragma unroll
        for (int nt = 0; nt < 4; nt++) {
            const int gc = n0 + wn + nt * 8 + c0;
            bias2[nt].x = bias[gc];
            bias2[nt].y = bias[gc + 1];
        }
    }

    #pragma unroll
    for (int mt = 0; mt < 4; mt++) {
        const int gr = m0 + wm + mt * 16 + r0;
        #pragma unroll
        for (int h = 0; h < 2; h++) {
            const int row = gr + h * 8;
            float* op = outF + (size_t)row * H_ + n0 + wn + c0;
            #pragma unroll
            for (int nt = 0; nt < 4; nt++) {
                float vx = acc[mt][nt][h * 2 + 0];
                float vy = acc[mt][nt][h * 2 + 1];
                if (G1) {
                    vx = fmaxf(vx + bias2[nt].x, 0.f);
                    vy = fmaxf(vy + bias2[nt].y, 0.f);
                }
                *(float2*)(op + nt * 8) = make_float2(vx, vy);
                if (G1) {
                    __half hx = __float2half_rn(vx), hy = __float2half_rn(vy);
                    __half lx = __float2half_rn(vx - __half2float(hx));
                    __half ly = __float2half_rn(vy - __half2float(hy));
                    const size_t off = (size_t)row * H_ + n0 + wn + c0 + nt * 8;
                    *(__half2*)(outHi + off) = __halves2half2(hx, hy);
                    *(__half2*)(outLo + off) = __halves2half2(lx, ly);
                }
            }
        }
    }
}

// ============================================================================
// Local windowed attention (unchanged)
// ============================================================================
#define TS 16
#define KC 128
#define HR (TS + 32)
#define HP 129

__global__ __launch_bounds__(256)
void atten_kernel(const float* __restrict__ h, const float* __restrict__ q,
                  float* __restrict__ out)
{
    __shared__ float qs[TS][KC];
    __shared__ float hs[HR][HP];
    __shared__ float sc[TS][AW + 3];

    const int tid = threadIdx.x;
    const int b = blockIdx.y;
    const int s0 = blockIdx.x * TS;

    const float* hB = h + (size_t)b * S_ * H_;
    const float* qB = q + (size_t)b * S_ * H_;
    float*       oB = out + (size_t)b * S_ * H_;

    int ps[3], pr[3];
    bool pv[3];
    float acc[3] = {0.f, 0.f, 0.f};
    #pragma unroll
    for (int u = 0; u < 3; u++) {
        const int p = tid + u * 256;
        pv[u] = (p < TS * AW);
        const int s = pv[u] ? (p / AW) : 0;
        const int w = pv[u] ? (p % AW) : 0;
        ps[u] = s;
        pr[u] = s + 32 - w;
    }

    for (int kc = 0; kc < H_; kc += KC) {
        for (int i = tid; i < TS * KC / 4; i += 256) {
            const int row = i / (KC / 4);
            const int col = (i % (KC / 4)) * 4;
            *(float4*)&qs[row][col] =
                *(const float4*)(qB + (size_t)(s0 + row) * H_ + kc + col);
        }
        for (int i = tid; i < HR * KC; i += 256) {
            const int r = i / KC;
            const int c = i % KC;
            const int g = s0 - 16 + r;
            hs[r][c] = (g >= 0 && g < S_) ? hB[(size_t)g * H_ + kc + c] : 0.f;
        }
        __syncthreads();

        #pragma unroll
        for (int u = 0; u < 3; u++) {
            if (pv[u]) {
                const float* qrow = qs[ps[u]];
                const float* hrow = hs[pr[u]];
                float sum = acc[u];
                #pragma unroll 8
                for (int k = 0; k < KC; k++)
                    sum += qrow[k] * hrow[k];
                acc[u] = sum;
            }
        }
        __syncthreads();
    }

    #pragma unroll
    for (int u = 0; u < 3; u++) {
        if (pv[u]) {
            const int p = tid + u * 256;
            sc[p / AW][p % AW] = acc[u] * 0.03125f;
        }
    }
    __syncthreads();

    if (tid < TS) {
        float m = -1e30f;
        for (int w = 0; w < AW; w++) m = fmaxf(m, sc[tid][w]);
        float sum = 0.f;
        for (int w = 0; w < AW; w++) {
            const float e = expf(sc[tid][w] - m);
            sc[tid][w] = e;
            sum += e;
        }
        const float inv = 1.f / sum;
        for (int w = 0; w < AW; w++) sc[tid][w] *= inv;
    }
    __syncthreads();

    for (int kc = 0; kc < H_; kc += KC) {
        for (int i = tid; i < HR * KC; i += 256) {
            const int r = i / KC;
            const int c = i % KC;
            const int g = s0 - 16 + r;
            hs[r][c] = (g >= 0 && g < S_) ? hB[(size_t)g * H_ + kc + c] : 0.f;
        }
        __syncthreads();

        for (int o = tid; o < TS * KC; o += 256) {
            const int s = o / KC;
            const int k = o % KC;
            float sum = 0.f;
            #pragma unroll
            for (int w = 0; w < AW; w++)
                sum += sc[s][w] * hs[s + 32 - w][k];
            oB[(size_t)(s0 + s) * H_ + kc + k] = sum;
        }
        __syncthreads();
    }
}

// ============================================================================
// Launch
// ============================================================================
extern "C" void kernel_launch(void* const* d_in, const int* in_sizes, int n_in,
                              void* d_out, int out_size)
{
    const float* x  = (const float*)d_in[0];   // [4,2048,512]
    const float* W1 = (const float*)d_in[1];   // [512,1024]
    const float* b1 = (const float*)d_in[2];   // [1024]
    const float* Wq = (const float*)d_in[3];   // [1024,1024]
    float* out = (float*)d_out;                // [4,2048,1024]

    float *hp, *qp;
    __half *xhi, *xlo, *hhi, *hlo, *w1thi, *w1tlo, *wqthi, *wqtlo;
    cudaGetSymbolAddress((void**)&hp, g_h);
    cudaGetSymbolAddress((void**)&qp, g_q);
    cudaGetSymbolAddress((void**)&xhi, g_xhi);
    cudaGetSymbolAddress((void**)&xlo, g_xlo);
    cudaGetSymbolAddress((void**)&hhi, g_hhi);
    cudaGetSymbolAddress((void**)&hlo, g_hlo);
    cudaGetSymbolAddress((void**)&w1thi, g_w1t_hi);
    cudaGetSymbolAddress((void**)&w1tlo, g_w1t_lo);
    cudaGetSymbolAddress((void**)&wqthi, g_wqt_hi);
    cudaGetSymbolAddress((void**)&wqtlo, g_wqt_lo);

    cudaFuncSetAttribute(hmma_gemm<true>,
                         cudaFuncAttributeMaxDynamicSharedMemorySize, GEMM_SMEM);
    cudaFuncSetAttribute(hmma_gemm<false>,
                         cudaFuncAttributeMaxDynamicSharedMemorySize, GEMM_SMEM);

    // Converts
    {
        int n4 = M_ * IN_ / 4;
        split_kernel<<<(n4 + 255) / 256, 256>>>(x, xhi, xlo, n4);
        dim3 t(32, 8);
        transpose_split_kernel<<<dim3(H_ / 32, IN_ / 32), t>>>(W1, w1thi, w1tlo, IN_, H_);
        transpose_split_kernel<<<dim3(H_ / 32, H_ / 32), t>>>(Wq, wqthi, wqtlo, H_, H_);
    }

    // GEMM1: h = relu(x @ W1 + b1)
    {
        dim3 grid(H_ / 128, M_ / 128);
        hmma_gemm<true><<<grid, 256, GEMM_SMEM>>>(
            xhi, xlo, w1thi, w1tlo, b1, hp, hhi, hlo, IN_);
    }
    // GEMM2: q = h @ Wq
    {
        dim3 grid(H_ / 128, M_ / 128);
        hmma_gemm<false><<<grid, 256, GEMM_SMEM>>>(
            hhi, hlo, wqthi, wqtlo, nullptr, qp, nullptr, nullptr, H_);
    }
    // Attention
    {
        dim3 grid(S_ / TS, B_);
        atten_kernel<<<grid, 256>>>(hp, qp, out);
    }
}

// round 5
// speedup vs baseline: 1.6656x; 1.1566x over previous
#include <cuda_runtime.h>
#include <cuda_fp16.h>
#include <math.h>
#include <stdint.h>

// ============================================================================
// Problem constants
// ============================================================================
#define B_   4
#define S_   2048
#define IN_  512
#define H_   1024
#define M_   (B_ * S_)   // 8192
#define AW   33          // 2*atten_size + 1

// ============================================================================
// Device global scratch (allocation-free per harness rules)
// ============================================================================
__device__ float g_h[(size_t)M_ * H_];
__device__ float g_q[(size_t)M_ * H_];

__device__ __half g_xhi[(size_t)M_ * IN_];
__device__ __half g_xlo[(size_t)M_ * IN_];
__device__ __half g_hhi[(size_t)M_ * H_];
__device__ __half g_hlo[(size_t)M_ * H_];
__device__ __half g_w1t_hi[(size_t)H_ * IN_];   // W1^T [1024,512]
__device__ __half g_w1t_lo[(size_t)H_ * IN_];
__device__ __half g_wqt_hi[(size_t)H_ * H_];    // Wq^T [1024,1024]
__device__ __half g_wqt_lo[(size_t)H_ * H_];

// ============================================================================
// PTX helpers (base sm_103 ISA only: cp.async, ldmatrix, mma.sync)
// ============================================================================
__device__ __forceinline__ uint32_t smem_u32(const void* p) {
    uint32_t a;
    asm("{ .reg .u64 t; cvta.to.shared.u64 t, %1; cvt.u32.u64 %0, t; }"
        : "=r"(a) : "l"(p));
    return a;
}

__device__ __forceinline__ void cp_async16(uint32_t dst, const void* src) {
    asm volatile("cp.async.cg.shared.global [%0], [%1], 16;"
                 :: "r"(dst), "l"(src));
}
#define CP_COMMIT() asm volatile("cp.async.commit_group;" ::: "memory")
#define CP_WAIT(n)  asm volatile("cp.async.wait_group %0;" :: "n"(n) : "memory")

__device__ __forceinline__ void ldsm_x4(uint32_t* r, uint32_t addr) {
    asm volatile("ldmatrix.sync.aligned.m8n8.x4.shared.b16 {%0,%1,%2,%3}, [%4];"
                 : "=r"(r[0]), "=r"(r[1]), "=r"(r[2]), "=r"(r[3]) : "r"(addr));
}

__device__ __forceinline__ void mma_f16(float* c, const uint32_t* a,
                                        uint32_t b0, uint32_t b1) {
    asm volatile(
        "mma.sync.aligned.m16n8k16.row.col.f32.f16.f16.f32 "
        "{%0,%1,%2,%3}, {%4,%5,%6,%7}, {%8,%9}, {%0,%1,%2,%3};"
        : "+f"(c[0]), "+f"(c[1]), "+f"(c[2]), "+f"(c[3])
        : "r"(a[0]), "r"(a[1]), "r"(a[2]), "r"(a[3]), "r"(b0), "r"(b1));
}

// ============================================================================
// Convert kernels: fp32 -> fp16 hi + fp16 lo (residual)
// ============================================================================
__global__ void split_kernel(const float* __restrict__ in,
                             __half* __restrict__ hi,
                             __half* __restrict__ lo, int n4) {
    int i = blockIdx.x * blockDim.x + threadIdx.x;
    if (i >= n4) return;
    float4 v = ((const float4*)in)[i];
    __half h0 = __float2half_rn(v.x), h1 = __float2half_rn(v.y);
    __half h2 = __float2half_rn(v.z), h3 = __float2half_rn(v.w);
    __half2 hp0 = __halves2half2(h0, h1), hp1 = __halves2half2(h2, h3);
    __half2 lp0 = __halves2half2(__float2half_rn(v.x - __half2float(h0)),
                                 __float2half_rn(v.y - __half2float(h1)));
    __half2 lp1 = __halves2half2(__float2half_rn(v.z - __half2float(h2)),
                                 __float2half_rn(v.w - __half2float(h3)));
    ((__half2*)hi)[i * 2 + 0] = hp0;
    ((__half2*)hi)[i * 2 + 1] = hp1;
    ((__half2*)lo)[i * 2 + 0] = lp0;
    ((__half2*)lo)[i * 2 + 1] = lp1;
}

// in [R, C] fp32 -> out^T [C, R] half hi/lo
__global__ void transpose_split_kernel(const float* __restrict__ in,
                                       __half* __restrict__ hiT,
                                       __half* __restrict__ loT,
                                       int R, int C) {
    __shared__ float t[32][33];
    const int c0 = blockIdx.x * 32, r0 = blockIdx.y * 32;
    const int tx = threadIdx.x, ty = threadIdx.y;   // 32 x 8
    #pragma unroll
    for (int j = 0; j < 32; j += 8)
        t[ty + j][tx] = in[(size_t)(r0 + ty + j) * C + c0 + tx];
    __syncthreads();
    #pragma unroll
    for (int j = 0; j < 32; j += 8) {
        float v = t[tx][ty + j];
        __half h = __float2half_rn(v);
        __half l = __float2half_rn(v - __half2float(h));
        size_t o = (size_t)(c0 + ty + j) * R + r0 + tx;
        hiT[o] = h;
        loT[o] = l;
    }
}

// ============================================================================
// HMMA split GEMM: C[M,N] = A[M,K] @ W[K,N], W given transposed [N,K].
// fp16 hi/lo split: C = AhiBhi + AhiBlo + AloBhi (fp32 accum).
// Block tile 128x128, BK=32, 16 warps (warp tile 32x32), 4-stage cp.async.
// SMEM row layout (128B): [hi k0..31 | lo k0..31], 16B groups XOR (row&7).
// ============================================================================
#define NST 4
#define STAGE_BYTES 32768   // A 16KB + B 16KB
#define GEMM_SMEM (NST * STAGE_BYTES)

template <bool G1>
__global__ __launch_bounds__(512, 1)
void hmma_gemm(const __half* __restrict__ Ahi, const __half* __restrict__ Alo,
               const __half* __restrict__ Bhi, const __half* __restrict__ Blo,
               const float* __restrict__ bias,
               float* __restrict__ outF,
               __half* __restrict__ outHi, __half* __restrict__ outLo,
               int K)
{
    extern __shared__ __align__(1024) char smem[];
    const uint32_t smBase = smem_u32(smem);

    const int tid  = threadIdx.x;
    const int wid  = tid >> 5;
    const int lane = tid & 31;
    const int m0 = blockIdx.y * 128;
    const int n0 = blockIdx.x * 128;
    const int nk = K / 32;

    const int wm = (wid & 3) * 32;    // warp m offset within block
    const int wn = (wid >> 2) * 32;   // warp n offset within block

    // --- loader mapping: each thread loads 4 16B-groups per stage ---
    const int half_sel = tid & 1;            // 0 -> hi, 1 -> lo
    const int lrow = (tid >> 1) & 127;       // 0..127
    const int is_b = tid >> 8;               // 0 -> A, 1 -> B
    const __half* srcA = (half_sel ? Alo : Ahi) + (size_t)(m0 + lrow) * K;
    const __half* srcB = (half_sel ? Blo : Bhi) + (size_t)(n0 + lrow) * K;
    const __half* src = is_b ? srcB : srcA;
    uint32_t dst[4];
    #pragma unroll
    for (int g = 0; g < 4; g++) {
        const int lg = half_sel * 4 + g;
        const int pg = (lg ^ (lrow & 7)) * 16;
        dst[g] = smBase + is_b * 16384 + lrow * 128 + pg;
    }

    auto load_stage = [&](int c, int s) {
        const __half* sp = src + c * 32;
        const uint32_t so = s * STAGE_BYTES;
        #pragma unroll
        for (int g = 0; g < 4; g++)
            cp_async16(dst[g] + so, sp + g * 8);
    };

    float acc[2][4][4];
    #pragma unroll
    for (int mt = 0; mt < 2; mt++)
        #pragma unroll
        for (int nt = 0; nt < 4; nt++)
            #pragma unroll
            for (int j = 0; j < 4; j++)
                acc[mt][nt][j] = 0.f;

    // prologue: fill NST-1 stages
    #pragma unroll
    for (int c = 0; c < NST - 1; c++) {
        load_stage(c, c);
        CP_COMMIT();
    }

    // fragment addressing (constant per thread)
    const int arow_l = (lane & 15);
    const int agrp_l = (lane >> 4);
    const int brow_l = (lane & 7) + ((lane >> 4) << 3);
    const int bgrp_l = (lane >> 3) & 1;

    for (int c = 0; c < nk; c++) {
        CP_WAIT(NST - 2);
        __syncthreads();
        // prefetch next stage (overwrites stage consumed in iter c-1; the
        // barrier above orders all consumers of that stage before these writes)
        if (c + NST - 1 < nk)
            load_stage(c + NST - 1, (c + NST - 1) % NST);
        CP_COMMIT();

        const uint32_t aB = smBase + (c % NST) * STAGE_BYTES;
        const uint32_t bB = aB + 16384;

        #pragma unroll
        for (int ks = 0; ks < 2; ks++) {
            uint32_t ahi[2][4], alo[2][4], bhi[2][4], blo[2][4];
            const int agH = ks * 2 + agrp_l;
            #pragma unroll
            for (int mt = 0; mt < 2; mt++) {
                const int row = wm + mt * 16 + arow_l;
                const uint32_t rb = aB + row * 128;
                ldsm_x4(ahi[mt], rb + ((agH ^ (row & 7)) * 16));
                ldsm_x4(alo[mt], rb + (((agH + 4) ^ (row & 7)) * 16));
            }
            const int bgH = ks * 2 + bgrp_l;
            #pragma unroll
            for (int np = 0; np < 2; np++) {
                const int row = wn + np * 16 + brow_l;
                const uint32_t rb = bB + row * 128;
                ldsm_x4(bhi[np], rb + ((bgH ^ (row & 7)) * 16));
                ldsm_x4(blo[np], rb + (((bgH + 4) ^ (row & 7)) * 16));
            }
            #pragma unroll
            for (int mt = 0; mt < 2; mt++) {
                #pragma unroll
                for (int nt = 0; nt < 4; nt++) {
                    const int np = nt >> 1, o = (nt & 1) * 2;
                    mma_f16(acc[mt][nt], ahi[mt], bhi[np][o], bhi[np][o + 1]);
                    mma_f16(acc[mt][nt], ahi[mt], blo[np][o], blo[np][o + 1]);
                    mma_f16(acc[mt][nt], alo[mt], bhi[np][o], bhi[np][o + 1]);
                }
            }
        }
    }

    // ---------------- epilogue ----------------
    const int r0 = lane >> 2;            // 0..7
    const int c0 = (lane & 3) * 2;

    float2 bias2[4];
    if (G1) {
        #pragma unroll
        for (int nt = 0; nt < 4; nt++) {
            const int gc = n0 + wn + nt * 8 + c0;
            bias2[nt].x = bias[gc];
            bias2[nt].y = bias[gc + 1];
        }
    }

    #pragma unroll
    for (int mt = 0; mt < 2; mt++) {
        const int gr = m0 + wm + mt * 16 + r0;
        #pragma unroll
        for (int h = 0; h < 2; h++) {
            const int row = gr + h * 8;
            float* op = outF + (size_t)row * H_ + n0 + wn + c0;
            #pragma unroll
            for (int nt = 0; nt < 4; nt++) {
                float vx = acc[mt][nt][h * 2 + 0];
                float vy = acc[mt][nt][h * 2 + 1];
                if (G1) {
                    vx = fmaxf(vx + bias2[nt].x, 0.f);
                    vy = fmaxf(vy + bias2[nt].y, 0.f);
                }
                *(float2*)(op + nt * 8) = make_float2(vx, vy);
                if (G1) {
                    __half hx = __float2half_rn(vx), hy = __float2half_rn(vy);
                    __half lx = __float2half_rn(vx - __half2float(hx));
                    __half ly = __float2half_rn(vy - __half2float(hy));
                    const size_t off = (size_t)row * H_ + n0 + wn + c0 + nt * 8;
                    *(__half2*)(outHi + off) = __halves2half2(hx, hy);
                    *(__half2*)(outLo + off) = __halves2half2(lx, ly);
                }
            }
        }
    }
}

// ============================================================================
// Local windowed attention — register-tiled.
// Block: (batch, 16 s-rows). hs holds 48-row neighborhood per 128-k chunk.
// Phase A: thread owns (s, 8-wide k slice); q in regs from gmem; 33 reg accs;
//          16-lane shfl reduction at the end.
// Phase C: thread owns 2 s-rows x 4 k; each hs float4 feeds both rows.
// ============================================================================
#define TS 16
#define KC 128
#define HR (TS + 32)   // 48
#define HPA 132        // hs pitch (float): 4-bank row offset

__global__ __launch_bounds__(256)
void atten_kernel(const float* __restrict__ h, const float* __restrict__ q,
                  float* __restrict__ out)
{
    __shared__ float hs[HR][HPA];       // ~25.3 KB
    __shared__ float sc[TS][AW + 3];

    const int tid = threadIdx.x;
    const int b = blockIdx.y;
    const int s0 = blockIdx.x * TS;

    const float* hB = h + (size_t)b * S_ * H_;
    const float* qB = q + (size_t)b * S_ * H_;
    float*       oB = out + (size_t)b * S_ * H_;

    const int warp = tid >> 5, lane = tid & 31;
    const int lane16 = lane & 15;
    const int sA = warp * 2 + (lane >> 4);   // 0..15
    const int kofs = lane16 * 8;

    // ---------------- Phase A: scores ----------------
    float acc[AW];
    #pragma unroll
    for (int w = 0; w < AW; w++) acc[w] = 0.f;

    for (int kc = 0; kc < H_; kc += KC) {
        __syncthreads();
        for (int i = tid; i < HR * (KC / 4); i += 256) {
            const int r = i >> 5;
            const int c4 = (i & 31) * 4;
            const int g = s0 - 16 + r;
            float4 v = make_float4(0.f, 0.f, 0.f, 0.f);
            if (g >= 0 && g < S_)
                v = *(const float4*)(hB + (size_t)g * H_ + kc + c4);
            *(float4*)&hs[r][c4] = v;
        }
        __syncthreads();

        const float* qp = qB + (size_t)(s0 + sA) * H_ + kc + kofs;
        const float4 qa = *(const float4*)qp;
        const float4 qb = *(const float4*)(qp + 4);

        #pragma unroll
        for (int w = 0; w < AW; w++) {
            const float* hr = &hs[sA + 32 - w][kofs];
            const float4 ha = *(const float4*)hr;
            const float4 hb = *(const float4*)(hr + 4);
            acc[w] += qa.x * ha.x + qa.y * ha.y + qa.z * ha.z + qa.w * ha.w
                    + qb.x * hb.x + qb.y * hb.y + qb.z * hb.z + qb.w * hb.w;
        }
    }

    // reduce across the 16 lanes of each s (xor <= 8 stays within half-warp)
    #pragma unroll
    for (int w = 0; w < AW; w++) {
        #pragma unroll
        for (int d = 8; d >= 1; d >>= 1)
            acc[w] += __shfl_xor_sync(0xffffffffu, acc[w], d);
    }
    #pragma unroll
    for (int w = 0; w < AW; w++) {
        if ((w & 15) == lane16 && (w < 32 || lane16 == 0))
            sc[sA][w] = acc[w] * 0.03125f;   // 1/sqrt(1024)
    }
    __syncthreads();

    // ---------------- Phase B: softmax (one thread per s) ----------------
    if (tid < TS) {
        float m = -1e30f;
        for (int w = 0; w < AW; w++) m = fmaxf(m, sc[tid][w]);
        float sum = 0.f;
        for (int w = 0; w < AW; w++) {
            const float e = expf(sc[tid][w] - m);
            sc[tid][w] = e;
            sum += e;
        }
        const float inv = 1.f / sum;
        for (int w = 0; w < AW; w++) sc[tid][w] *= inv;
    }

    // ---------------- Phase C: weighted sum ----------------
    const int sg = (tid >> 5) * 2;       // even s of the pair
    const int kq = (tid & 31) * 4;

    for (int kc = 0; kc < H_; kc += KC) {
        __syncthreads();
        for (int i = tid; i < HR * (KC / 4); i += 256) {
            const int r = i >> 5;
            const int c4 = (i & 31) * 4;
            const int g = s0 - 16 + r;
            float4 v = make_float4(0.f, 0.f, 0.f, 0.f);
            if (g >= 0 && g < S_)
                v = *(const float4*)(hB + (size_t)g * H_ + kc + c4);
            *(float4*)&hs[r][c4] = v;
        }
        __syncthreads();

        float4 a0 = make_float4(0.f, 0.f, 0.f, 0.f);
        float4 a1 = make_float4(0.f, 0.f, 0.f, 0.f);
        #pragma unroll
        for (int j = 0; j < 34; j++) {
            const float4 h4 = *(const float4*)&hs[sg + j][kq];
            if (j <= 32) {
                const float p = sc[sg][32 - j];
                a0.x += p * h4.x; a0.y += p * h4.y;
                a0.z += p * h4.z; a0.w += p * h4.w;
            }
            if (j >= 1) {
                const float p = sc[sg + 1][33 - j];
                a1.x += p * h4.x; a1.y += p * h4.y;
                a1.z += p * h4.z; a1.w += p * h4.w;
            }
        }
        *(float4*)(oB + (size_t)(s0 + sg) * H_ + kc + kq) = a0;
        *(float4*)(oB + (size_t)(s0 + sg + 1) * H_ + kc + kq) = a1;
    }
}

// ============================================================================
// Launch
// ============================================================================
extern "C" void kernel_launch(void* const* d_in, const int* in_sizes, int n_in,
                              void* d_out, int out_size)
{
    const float* x  = (const float*)d_in[0];   // [4,2048,512]
    const float* W1 = (const float*)d_in[1];   // [512,1024]
    const float* b1 = (const float*)d_in[2];   // [1024]
    const float* Wq = (const float*)d_in[3];   // [1024,1024]
    float* out = (float*)d_out;                // [4,2048,1024]

    float *hp, *qp;
    __half *xhi, *xlo, *hhi, *hlo, *w1thi, *w1tlo, *wqthi, *wqtlo;
    cudaGetSymbolAddress((void**)&hp, g_h);
    cudaGetSymbolAddress((void**)&qp, g_q);
    cudaGetSymbolAddress((void**)&xhi, g_xhi);
    cudaGetSymbolAddress((void**)&xlo, g_xlo);
    cudaGetSymbolAddress((void**)&hhi, g_hhi);
    cudaGetSymbolAddress((void**)&hlo, g_hlo);
    cudaGetSymbolAddress((void**)&w1thi, g_w1t_hi);
    cudaGetSymbolAddress((void**)&w1tlo, g_w1t_lo);
    cudaGetSymbolAddress((void**)&wqthi, g_wqt_hi);
    cudaGetSymbolAddress((void**)&wqtlo, g_wqt_lo);

    cudaFuncSetAttribute(hmma_gemm<true>,
                         cudaFuncAttributeMaxDynamicSharedMemorySize, GEMM_SMEM);
    cudaFuncSetAttribute(hmma_gemm<false>,
                         cudaFuncAttributeMaxDynamicSharedMemorySize, GEMM_SMEM);

    // Converts
    {
        int n4 = M_ * IN_ / 4;
        split_kernel<<<(n4 + 255) / 256, 256>>>(x, xhi, xlo, n4);
        dim3 t(32, 8);
        transpose_split_kernel<<<dim3(H_ / 32, IN_ / 32), t>>>(W1, w1thi, w1tlo, IN_, H_);
        transpose_split_kernel<<<dim3(H_ / 32, H_ / 32), t>>>(Wq, wqthi, wqtlo, H_, H_);
    }

    // GEMM1: h = relu(x @ W1 + b1)
    {
        dim3 grid(H_ / 128, M_ / 128);
        hmma_gemm<true><<<grid, 512, GEMM_SMEM>>>(
            xhi, xlo, w1thi, w1tlo, b1, hp, hhi, hlo, IN_);
    }
    // GEMM2: q = h @ Wq
    {
        dim3 grid(H_ / 128, M_ / 128);
        hmma_gemm<false><<<grid, 512, GEMM_SMEM>>>(
            hhi, hlo, wqthi, wqtlo, nullptr, qp, nullptr, nullptr, H_);
    }
    // Attention
    {
        dim3 grid(S_ / TS, B_);
        atten_kernel<<<grid, 256>>>(hp, qp, out);
    }
}

// round 6
// speedup vs baseline: 1.8021x; 1.0820x over previous
#include <cuda_runtime.h>
#include <cuda_fp16.h>
#include <math.h>
#include <stdint.h>

// ============================================================================
// Problem constants
// ============================================================================
#define B_   4
#define S_   2048
#define IN_  512
#define H_   1024
#define M_   (B_ * S_)   // 8192
#define AW   33          // 2*atten_size + 1

// ============================================================================
// Device global scratch (allocation-free per harness rules)
// ============================================================================
__device__ float g_h[(size_t)M_ * H_];
__device__ float g_q[(size_t)M_ * H_];

__device__ __half g_xhi[(size_t)M_ * IN_];
__device__ __half g_xlo[(size_t)M_ * IN_];
__device__ __half g_hhi[(size_t)M_ * H_];
__device__ __half g_hlo[(size_t)M_ * H_];
__device__ __half g_w1t_hi[(size_t)H_ * IN_];   // W1^T [1024,512]
__device__ __half g_w1t_lo[(size_t)H_ * IN_];
__device__ __half g_wqt_hi[(size_t)H_ * H_];    // Wq^T [1024,1024]
__device__ __half g_wqt_lo[(size_t)H_ * H_];

// ============================================================================
// PTX helpers (base sm_103 ISA only: cp.async, ldmatrix, mma.sync)
// ============================================================================
__device__ __forceinline__ uint32_t smem_u32(const void* p) {
    uint32_t a;
    asm("{ .reg .u64 t; cvta.to.shared.u64 t, %1; cvt.u32.u64 %0, t; }"
        : "=r"(a) : "l"(p));
    return a;
}

__device__ __forceinline__ void cp_async16(uint32_t dst, const void* src) {
    asm volatile("cp.async.cg.shared.global [%0], [%1], 16;"
                 :: "r"(dst), "l"(src));
}
#define CP_COMMIT() asm volatile("cp.async.commit_group;" ::: "memory")
#define CP_WAIT(n)  asm volatile("cp.async.wait_group %0;" :: "n"(n) : "memory")

__device__ __forceinline__ void ldsm_x4(uint32_t* r, uint32_t addr) {
    asm volatile("ldmatrix.sync.aligned.m8n8.x4.shared.b16 {%0,%1,%2,%3}, [%4];"
                 : "=r"(r[0]), "=r"(r[1]), "=r"(r[2]), "=r"(r[3]) : "r"(addr));
}

__device__ __forceinline__ void mma_f16(float* c, const uint32_t* a,
                                        uint32_t b0, uint32_t b1) {
    asm volatile(
        "mma.sync.aligned.m16n8k16.row.col.f32.f16.f16.f32 "
        "{%0,%1,%2,%3}, {%4,%5,%6,%7}, {%8,%9}, {%0,%1,%2,%3};"
        : "+f"(c[0]), "+f"(c[1]), "+f"(c[2]), "+f"(c[3])
        : "r"(a[0]), "r"(a[1]), "r"(a[2]), "r"(a[3]), "r"(b0), "r"(b1));
}

// ============================================================================
// Convert kernels: fp32 -> fp16 hi + fp16 lo (residual)
// ============================================================================
__global__ void split_kernel(const float* __restrict__ in,
                             __half* __restrict__ hi,
                             __half* __restrict__ lo, int n4) {
    int i = blockIdx.x * blockDim.x + threadIdx.x;
    if (i >= n4) return;
    float4 v = ((const float4*)in)[i];
    __half h0 = __float2half_rn(v.x), h1 = __float2half_rn(v.y);
    __half h2 = __float2half_rn(v.z), h3 = __float2half_rn(v.w);
    __half2 hp0 = __halves2half2(h0, h1), hp1 = __halves2half2(h2, h3);
    __half2 lp0 = __halves2half2(__float2half_rn(v.x - __half2float(h0)),
                                 __float2half_rn(v.y - __half2float(h1)));
    __half2 lp1 = __halves2half2(__float2half_rn(v.z - __half2float(h2)),
                                 __float2half_rn(v.w - __half2float(h3)));
    ((__half2*)hi)[i * 2 + 0] = hp0;
    ((__half2*)hi)[i * 2 + 1] = hp1;
    ((__half2*)lo)[i * 2 + 0] = lp0;
    ((__half2*)lo)[i * 2 + 1] = lp1;
}

// in [R, C] fp32 -> out^T [C, R] half hi/lo
__global__ void transpose_split_kernel(const float* __restrict__ in,
                                       __half* __restrict__ hiT,
                                       __half* __restrict__ loT,
                                       int R, int C) {
    __shared__ float t[32][33];
    const int c0 = blockIdx.x * 32, r0 = blockIdx.y * 32;
    const int tx = threadIdx.x, ty = threadIdx.y;   // 32 x 8
    #pragma unroll
    for (int j = 0; j < 32; j += 8)
        t[ty + j][tx] = in[(size_t)(r0 + ty + j) * C + c0 + tx];
    __syncthreads();
    #pragma unroll
    for (int j = 0; j < 32; j += 8) {
        float v = t[tx][ty + j];
        __half h = __float2half_rn(v);
        __half l = __float2half_rn(v - __half2float(h));
        size_t o = (size_t)(c0 + ty + j) * R + r0 + tx;
        hiT[o] = h;
        loT[o] = l;
    }
}

// ============================================================================
// HMMA split GEMM: C[M,N] = A[M,K] @ W[K,N], W given transposed [N,K].
// fp16 hi/lo split: C = AhiBhi + AhiBlo + AloBhi (fp32 accum).
// Block tile 256x128, BK=32, 8 warps (warp tile 64x64), 4-stage cp.async.
// SMEM row layout (128B): [hi k0..31 | lo k0..31], 16B groups XOR (row&7).
// MMA issued term-major so accumulator reuse distance is 8 (no RAW stalls).
// ============================================================================
#define NST 4
#define A_BYTES 32768                    // 256 rows x 128B
#define STAGE_BYTES (A_BYTES + 16384)    // + B: 128 rows x 128B
#define GEMM_SMEM (NST * STAGE_BYTES)

template <bool G1>
__global__ __launch_bounds__(256, 1)
void hmma_gemm(const __half* __restrict__ Ahi, const __half* __restrict__ Alo,
               const __half* __restrict__ Bhi, const __half* __restrict__ Blo,
               const float* __restrict__ bias,
               float* __restrict__ outF,
               __half* __restrict__ outHi, __half* __restrict__ outLo,
               int K)
{
    extern __shared__ __align__(1024) char smem[];
    const uint32_t smBase = smem_u32(smem);

    const int tid  = threadIdx.x;
    const int wid  = tid >> 5;
    const int lane = tid & 31;
    const int m0 = blockIdx.y * 256;
    const int n0 = blockIdx.x * 128;
    const int nk = K / 32;

    const int wm = (wid & 3) * 64;    // warp m offset within block
    const int wn = (wid >> 2) * 64;   // warp n offset within block

    // --- loader mapping: each thread: 2 A rows (4 groups each) + 1 B row ---
    const int half_sel = tid & 1;            // 0 -> hi, 1 -> lo
    const int lrow = tid >> 1;               // 0..127
    const __half* srcA0 = (half_sel ? Alo : Ahi) + (size_t)(m0 + lrow) * K;
    const __half* srcA1 = (half_sel ? Alo : Ahi) + (size_t)(m0 + lrow + 128) * K;
    const __half* srcB  = (half_sel ? Blo : Bhi) + (size_t)(n0 + lrow) * K;
    uint32_t dstA0[4], dstA1[4], dstB[4];
    #pragma unroll
    for (int g = 0; g < 4; g++) {
        const int lg = half_sel * 4 + g;
        const int pg = (lg ^ (lrow & 7)) * 16;
        dstA0[g] = smBase + lrow * 128 + pg;
        dstA1[g] = smBase + (lrow + 128) * 128 + pg;   // same (row&7)
        dstB[g]  = smBase + A_BYTES + lrow * 128 + pg;
    }

    auto load_stage = [&](int c, int s) {
        const __half* sa0 = srcA0 + c * 32;
        const __half* sa1 = srcA1 + c * 32;
        const __half* sb  = srcB  + c * 32;
        const uint32_t so = s * STAGE_BYTES;
        #pragma unroll
        for (int g = 0; g < 4; g++) {
            cp_async16(dstA0[g] + so, sa0 + g * 8);
            cp_async16(dstA1[g] + so, sa1 + g * 8);
            cp_async16(dstB[g]  + so, sb  + g * 8);
        }
    };

    float acc[4][8][4];
    #pragma unroll
    for (int mt = 0; mt < 4; mt++)
        #pragma unroll
        for (int nt = 0; nt < 8; nt++)
            #pragma unroll
            for (int j = 0; j < 4; j++)
                acc[mt][nt][j] = 0.f;

    // prologue: fill NST-1 stages
    #pragma unroll
    for (int c = 0; c < NST - 1; c++) {
        load_stage(c, c);
        CP_COMMIT();
    }

    // fragment addressing (constant per thread)
    const int arow_l = (lane & 15);
    const int agrp_l = (lane >> 4);
    const int brow_l = (lane & 7) + ((lane >> 4) << 3);
    const int bgrp_l = (lane >> 3) & 1;

    for (int c = 0; c < nk; c++) {
        CP_WAIT(NST - 2);
        __syncthreads();
        if (c + NST - 1 < nk)
            load_stage(c + NST - 1, (c + NST - 1) % NST);
        CP_COMMIT();

        const uint32_t aB = smBase + (c % NST) * STAGE_BYTES;
        const uint32_t bB = aB + A_BYTES;

        #pragma unroll
        for (int ks = 0; ks < 2; ks++) {
            const int agH = ks * 2 + agrp_l;
            const int bgH = ks * 2 + bgrp_l;

            uint32_t bhi[4][4], blo[4][4];
            #pragma unroll
            for (int np = 0; np < 4; np++) {
                const int row = wn + np * 16 + brow_l;
                const uint32_t rb = bB + row * 128;
                ldsm_x4(bhi[np], rb + ((bgH ^ (row & 7)) * 16));
                ldsm_x4(blo[np], rb + (((bgH + 4) ^ (row & 7)) * 16));
            }

            #pragma unroll
            for (int mt = 0; mt < 4; mt++) {
                const int row = wm + mt * 16 + arow_l;
                const uint32_t ra = aB + row * 128;
                uint32_t ahi[4], alo[4];
                ldsm_x4(ahi, ra + ((agH ^ (row & 7)) * 16));
                ldsm_x4(alo, ra + (((agH + 4) ^ (row & 7)) * 16));
                // term-major: reuse distance 8 per accumulator
                #pragma unroll
                for (int nt = 0; nt < 8; nt++) {
                    const int np = nt >> 1, o = (nt & 1) * 2;
                    mma_f16(acc[mt][nt], ahi, bhi[np][o], bhi[np][o + 1]);
                }
                #pragma unroll
                for (int nt = 0; nt < 8; nt++) {
                    const int np = nt >> 1, o = (nt & 1) * 2;
                    mma_f16(acc[mt][nt], ahi, blo[np][o], blo[np][o + 1]);
                }
                #pragma unroll
                for (int nt = 0; nt < 8; nt++) {
                    const int np = nt >> 1, o = (nt & 1) * 2;
                    mma_f16(acc[mt][nt], alo, bhi[np][o], bhi[np][o + 1]);
                }
            }
        }
    }

    // ---------------- epilogue ----------------
    const int r0 = lane >> 2;            // 0..7
    const int c0 = (lane & 3) * 2;

    float2 bias2[8];
    if (G1) {
        #pragma unroll
        for (int nt = 0; nt < 8; nt++) {
            const int gc = n0 + wn + nt * 8 + c0;
            bias2[nt].x = bias[gc];
            bias2[nt].y = bias[gc + 1];
        }
    }

    #pragma unroll
    for (int mt = 0; mt < 4; mt++) {
        #pragma unroll
        for (int h = 0; h < 2; h++) {
            const int row = m0 + wm + mt * 16 + h * 8 + r0;
            float* op = outF + (size_t)row * H_ + n0 + wn + c0;
            #pragma unroll
            for (int nt = 0; nt < 8; nt++) {
                float vx = acc[mt][nt][h * 2 + 0];
                float vy = acc[mt][nt][h * 2 + 1];
                if (G1) {
                    vx = fmaxf(vx + bias2[nt].x, 0.f);
                    vy = fmaxf(vy + bias2[nt].y, 0.f);
                }
                *(float2*)(op + nt * 8) = make_float2(vx, vy);
                if (G1) {
                    __half hx = __float2half_rn(vx), hy = __float2half_rn(vy);
                    __half lx = __float2half_rn(vx - __half2float(hx));
                    __half ly = __float2half_rn(vy - __half2float(hy));
                    const size_t off = (size_t)row * H_ + n0 + wn + c0 + nt * 8;
                    *(__half2*)(outHi + off) = __halves2half2(hx, hy);
                    *(__half2*)(outLo + off) = __halves2half2(lx, ly);
                }
            }
        }
    }
}

// ============================================================================
// Local windowed attention — register-tiled (unchanged from round 5)
// ============================================================================
#define TS 16
#define KC 128
#define HR (TS + 32)   // 48
#define HPA 132        // hs pitch (float)

__global__ __launch_bounds__(256)
void atten_kernel(const float* __restrict__ h, const float* __restrict__ q,
                  float* __restrict__ out)
{
    __shared__ float hs[HR][HPA];
    __shared__ float sc[TS][AW + 3];

    const int tid = threadIdx.x;
    const int b = blockIdx.y;
    const int s0 = blockIdx.x * TS;

    const float* hB = h + (size_t)b * S_ * H_;
    const float* qB = q + (size_t)b * S_ * H_;
    float*       oB = out + (size_t)b * S_ * H_;

    const int warp = tid >> 5, lane = tid & 31;
    const int lane16 = lane & 15;
    const int sA = warp * 2 + (lane >> 4);
    const int kofs = lane16 * 8;

    // ---------------- Phase A: scores ----------------
    float acc[AW];
    #pragma unroll
    for (int w = 0; w < AW; w++) acc[w] = 0.f;

    for (int kc = 0; kc < H_; kc += KC) {
        __syncthreads();
        for (int i = tid; i < HR * (KC / 4); i += 256) {
            const int r = i >> 5;
            const int c4 = (i & 31) * 4;
            const int g = s0 - 16 + r;
            float4 v = make_float4(0.f, 0.f, 0.f, 0.f);
            if (g >= 0 && g < S_)
                v = *(const float4*)(hB + (size_t)g * H_ + kc + c4);
            *(float4*)&hs[r][c4] = v;
        }
        __syncthreads();

        const float* qp = qB + (size_t)(s0 + sA) * H_ + kc + kofs;
        const float4 qa = *(const float4*)qp;
        const float4 qb = *(const float4*)(qp + 4);

        #pragma unroll
        for (int w = 0; w < AW; w++) {
            const float* hr = &hs[sA + 32 - w][kofs];
            const float4 ha = *(const float4*)hr;
            const float4 hb = *(const float4*)(hr + 4);
            acc[w] += qa.x * ha.x + qa.y * ha.y + qa.z * ha.z + qa.w * ha.w
                    + qb.x * hb.x + qb.y * hb.y + qb.z * hb.z + qb.w * hb.w;
        }
    }

    #pragma unroll
    for (int w = 0; w < AW; w++) {
        #pragma unroll
        for (int d = 8; d >= 1; d >>= 1)
            acc[w] += __shfl_xor_sync(0xffffffffu, acc[w], d);
    }
    #pragma unroll
    for (int w = 0; w < AW; w++) {
        if ((w & 15) == lane16 && (w < 32 || lane16 == 0))
            sc[sA][w] = acc[w] * 0.03125f;
    }
    __syncthreads();

    // ---------------- Phase B: softmax ----------------
    if (tid < TS) {
        float m = -1e30f;
        for (int w = 0; w < AW; w++) m = fmaxf(m, sc[tid][w]);
        float sum = 0.f;
        for (int w = 0; w < AW; w++) {
            const float e = expf(sc[tid][w] - m);
            sc[tid][w] = e;
            sum += e;
        }
        const float inv = 1.f / sum;
        for (int w = 0; w < AW; w++) sc[tid][w] *= inv;
    }

    // ---------------- Phase C: weighted sum ----------------
    const int sg = (tid >> 5) * 2;
    const int kq = (tid & 31) * 4;

    for (int kc = 0; kc < H_; kc += KC) {
        __syncthreads();
        for (int i = tid; i < HR * (KC / 4); i += 256) {
            const int r = i >> 5;
            const int c4 = (i & 31) * 4;
            const int g = s0 - 16 + r;
            float4 v = make_float4(0.f, 0.f, 0.f, 0.f);
            if (g >= 0 && g < S_)
                v = *(const float4*)(hB + (size_t)g * H_ + kc + c4);
            *(float4*)&hs[r][c4] = v;
        }
        __syncthreads();

        float4 a0 = make_float4(0.f, 0.f, 0.f, 0.f);
        float4 a1 = make_float4(0.f, 0.f, 0.f, 0.f);
        #pragma unroll
        for (int j = 0; j < 34; j++) {
            const float4 h4 = *(const float4*)&hs[sg + j][kq];
            if (j <= 32) {
                const float p = sc[sg][32 - j];
                a0.x += p * h4.x; a0.y += p * h4.y;
                a0.z += p * h4.z; a0.w += p * h4.w;
            }
            if (j >= 1) {
                const float p = sc[sg + 1][33 - j];
                a1.x += p * h4.x; a1.y += p * h4.y;
                a1.z += p * h4.z; a1.w += p * h4.w;
            }
        }
        *(float4*)(oB + (size_t)(s0 + sg) * H_ + kc + kq) = a0;
        *(float4*)(oB + (size_t)(s0 + sg + 1) * H_ + kc + kq) = a1;
    }
}

// ============================================================================
// Launch
// ============================================================================
extern "C" void kernel_launch(void* const* d_in, const int* in_sizes, int n_in,
                              void* d_out, int out_size)
{
    const float* x  = (const float*)d_in[0];   // [4,2048,512]
    const float* W1 = (const float*)d_in[1];   // [512,1024]
    const float* b1 = (const float*)d_in[2];   // [1024]
    const float* Wq = (const float*)d_in[3];   // [1024,1024]
    float* out = (float*)d_out;                // [4,2048,1024]

    float *hp, *qp;
    __half *xhi, *xlo, *hhi, *hlo, *w1thi, *w1tlo, *wqthi, *wqtlo;
    cudaGetSymbolAddress((void**)&hp, g_h);
    cudaGetSymbolAddress((void**)&qp, g_q);
    cudaGetSymbolAddress((void**)&xhi, g_xhi);
    cudaGetSymbolAddress((void**)&xlo, g_xlo);
    cudaGetSymbolAddress((void**)&hhi, g_hhi);
    cudaGetSymbolAddress((void**)&hlo, g_hlo);
    cudaGetSymbolAddress((void**)&w1thi, g_w1t_hi);
    cudaGetSymbolAddress((void**)&w1tlo, g_w1t_lo);
    cudaGetSymbolAddress((void**)&wqthi, g_wqt_hi);
    cudaGetSymbolAddress((void**)&wqtlo, g_wqt_lo);

    cudaFuncSetAttribute(hmma_gemm<true>,
                         cudaFuncAttributeMaxDynamicSharedMemorySize, GEMM_SMEM);
    cudaFuncSetAttribute(hmma_gemm<false>,
                         cudaFuncAttributeMaxDynamicSharedMemorySize, GEMM_SMEM);

    // Converts
    {
        int n4 = M_ * IN_ / 4;
        split_kernel<<<(n4 + 255) / 256, 256>>>(x, xhi, xlo, n4);
        dim3 t(32, 8);
        transpose_split_kernel<<<dim3(H_ / 32, IN_ / 32), t>>>(W1, w1thi, w1tlo, IN_, H_);
        transpose_split_kernel<<<dim3(H_ / 32, H_ / 32), t>>>(Wq, wqthi, wqtlo, H_, H_);
    }

    // GEMM1: h = relu(x @ W1 + b1)
    {
        dim3 grid(H_ / 128, M_ / 256);
        hmma_gemm<true><<<grid, 256, GEMM_SMEM>>>(
            xhi, xlo, w1thi, w1tlo, b1, hp, hhi, hlo, IN_);
    }
    // GEMM2: q = h @ Wq
    {
        dim3 grid(H_ / 128, M_ / 256);
        hmma_gemm<false><<<grid, 256, GEMM_SMEM>>>(
            hhi, hlo, wqthi, wqtlo, nullptr, qp, nullptr, nullptr, H_);
    }
    // Attention
    {
        dim3 grid(S_ / TS, B_);
        atten_kernel<<<grid, 256>>>(hp, qp, out);
    }
}

// round 7
// speedup vs baseline: 2.1833x; 1.2115x over previous
#include <cuda_runtime.h>
#include <cuda_fp16.h>
#include <math.h>
#include <stdint.h>

// ============================================================================
// Problem constants
// ============================================================================
#define B_   4
#define S_   2048
#define IN_  512
#define H_   1024
#define M_   (B_ * S_)   // 8192
#define AW   33          // 2*atten_size + 1

// ============================================================================
// Device global scratch (allocation-free per harness rules)
// ============================================================================
__device__ float g_h[(size_t)M_ * H_];
__device__ float g_q[(size_t)M_ * H_];

__device__ __half g_xhi[(size_t)M_ * IN_];
__device__ __half g_xlo[(size_t)M_ * IN_];
__device__ __half g_hhi[(size_t)M_ * H_];
__device__ __half g_w1t_hi[(size_t)H_ * IN_];   // W1^T [1024,512]
__device__ __half g_w1t_lo[(size_t)H_ * IN_];
__device__ __half g_wqt_hi[(size_t)H_ * H_];    // Wq^T [1024,1024]
__device__ __half g_wqt_lo[(size_t)H_ * H_];

// ============================================================================
// PTX helpers (base sm_103 ISA only: cp.async, ldmatrix, mma.sync)
// ============================================================================
__device__ __forceinline__ uint32_t smem_u32(const void* p) {
    uint32_t a;
    asm("{ .reg .u64 t; cvta.to.shared.u64 t, %1; cvt.u32.u64 %0, t; }"
        : "=r"(a) : "l"(p));
    return a;
}

__device__ __forceinline__ void cp_async16(uint32_t dst, const void* src) {
    asm volatile("cp.async.cg.shared.global [%0], [%1], 16;"
                 :: "r"(dst), "l"(src));
}
#define CP_COMMIT() asm volatile("cp.async.commit_group;" ::: "memory")
#define CP_WAIT(n)  asm volatile("cp.async.wait_group %0;" :: "n"(n) : "memory")

__device__ __forceinline__ void ldsm_x4(uint32_t* r, uint32_t addr) {
    asm volatile("ldmatrix.sync.aligned.m8n8.x4.shared.b16 {%0,%1,%2,%3}, [%4];"
                 : "=r"(r[0]), "=r"(r[1]), "=r"(r[2]), "=r"(r[3]) : "r"(addr));
}

__device__ __forceinline__ void mma_f16(float* c, const uint32_t* a,
                                        uint32_t b0, uint32_t b1) {
    asm volatile(
        "mma.sync.aligned.m16n8k16.row.col.f32.f16.f16.f32 "
        "{%0,%1,%2,%3}, {%4,%5,%6,%7}, {%8,%9}, {%0,%1,%2,%3};"
        : "+f"(c[0]), "+f"(c[1]), "+f"(c[2]), "+f"(c[3])
        : "r"(a[0]), "r"(a[1]), "r"(a[2]), "r"(a[3]), "r"(b0), "r"(b1));
}

// ============================================================================
// Convert kernels: fp32 -> fp16 hi + fp16 lo (residual)
// ============================================================================
__global__ void split_kernel(const float* __restrict__ in,
                             __half* __restrict__ hi,
                             __half* __restrict__ lo, int n4) {
    int i = blockIdx.x * blockDim.x + threadIdx.x;
    if (i >= n4) return;
    float4 v = ((const float4*)in)[i];
    __half h0 = __float2half_rn(v.x), h1 = __float2half_rn(v.y);
    __half h2 = __float2half_rn(v.z), h3 = __float2half_rn(v.w);
    __half2 hp0 = __halves2half2(h0, h1), hp1 = __halves2half2(h2, h3);
    __half2 lp0 = __halves2half2(__float2half_rn(v.x - __half2float(h0)),
                                 __float2half_rn(v.y - __half2float(h1)));
    __half2 lp1 = __halves2half2(__float2half_rn(v.z - __half2float(h2)),
                                 __float2half_rn(v.w - __half2float(h3)));
    ((__half2*)hi)[i * 2 + 0] = hp0;
    ((__half2*)hi)[i * 2 + 1] = hp1;
    ((__half2*)lo)[i * 2 + 0] = lp0;
    ((__half2*)lo)[i * 2 + 1] = lp1;
}

// in [R, C] fp32 -> out^T [C, R] half hi/lo
__global__ void transpose_split_kernel(const float* __restrict__ in,
                                       __half* __restrict__ hiT,
                                       __half* __restrict__ loT,
                                       int R, int C) {
    __shared__ float t[32][33];
    const int c0 = blockIdx.x * 32, r0 = blockIdx.y * 32;
    const int tx = threadIdx.x, ty = threadIdx.y;   // 32 x 8
    #pragma unroll
    for (int j = 0; j < 32; j += 8)
        t[ty + j][tx] = in[(size_t)(r0 + ty + j) * C + c0 + tx];
    __syncthreads();
    #pragma unroll
    for (int j = 0; j < 32; j += 8) {
        float v = t[tx][ty + j];
        __half h = __float2half_rn(v);
        __half l = __float2half_rn(v - __half2float(h));
        size_t o = (size_t)(c0 + ty + j) * R + r0 + tx;
        hiT[o] = h;
        loT[o] = l;
    }
}

// ============================================================================
// HMMA split GEMM: C[M,N] = A[M,K] @ W[K,N], W given transposed [N,K].
// TERMS==3: C = AhiBhi + AhiBlo + AloBhi.  TERMS==2: C = Ahi(Bhi+Blo).
// Block tile 256x128, BK=32, 16 warps (warp tile 64x32), 4-stage cp.async.
// SMEM row layout (128B): [hi k0..31 | lo k0..31], 16B groups XOR (row&7).
// ~115 regs/thread (no spill), 4 warps/SMSP.
// ============================================================================
#define NST 4
#define A_BYTES 32768                    // 256 rows x 128B
#define STAGE_BYTES (A_BYTES + 16384)    // + B: 128 rows x 128B
#define GEMM_SMEM (NST * STAGE_BYTES)    // 192 KB

template <int TERMS, bool G1>
__global__ __launch_bounds__(512, 1)
void hmma_gemm(const __half* __restrict__ Ahi, const __half* __restrict__ Alo,
               const __half* __restrict__ Bhi, const __half* __restrict__ Blo,
               const float* __restrict__ bias,
               float* __restrict__ outF,
               __half* __restrict__ outHi,
               int K)
{
    extern __shared__ __align__(1024) char smem[];
    const uint32_t smBase = smem_u32(smem);

    const int tid  = threadIdx.x;
    const int wid  = tid >> 5;
    const int lane = tid & 31;
    const int m0 = blockIdx.y * 256;
    const int n0 = blockIdx.x * 128;
    const int nk = K / 32;

    const int wm = (wid & 3) * 64;    // warp m offset within block
    const int wn = (wid >> 2) * 32;   // warp n offset within block

    // --- loader mapping ---
    // A: 512 threads, each one hi- or lo-half (4x16B) of one of 256 rows.
    // B: threads 0..255, each one hi- or lo-half of one of 128 rows.
    const int half_sel = tid & 1;             // 0 -> hi, 1 -> lo
    const int arow = tid >> 1;                // 0..255
    const bool loadA = (TERMS == 3) || (half_sel == 0);
    const bool loadB = tid < 256;
    const int brow = (tid >> 1) & 127;
    const __half* srcA = (half_sel ? Alo : Ahi) + (size_t)(m0 + arow) * K;
    const __half* srcB = (half_sel ? Blo : Bhi) + (size_t)(n0 + brow) * K;
    uint32_t dstA[4], dstB[4];
    #pragma unroll
    for (int g = 0; g < 4; g++) {
        const int lg = half_sel * 4 + g;
        dstA[g] = smBase + arow * 128 + ((lg ^ (arow & 7)) * 16);
        dstB[g] = smBase + A_BYTES + brow * 128 + ((lg ^ (brow & 7)) * 16);
    }

    auto load_stage = [&](int c, int s) {
        const uint32_t so = s * STAGE_BYTES;
        if (loadA) {
            const __half* sa = srcA + c * 32;
            #pragma unroll
            for (int g = 0; g < 4; g++)
                cp_async16(dstA[g] + so, sa + g * 8);
        }
        if (loadB) {
            const __half* sb = srcB + c * 32;
            #pragma unroll
            for (int g = 0; g < 4; g++)
                cp_async16(dstB[g] + so, sb + g * 8);
        }
    };

    float acc[4][4][4];
    #pragma unroll
    for (int mt = 0; mt < 4; mt++)
        #pragma unroll
        for (int nt = 0; nt < 4; nt++)
            #pragma unroll
            for (int j = 0; j < 4; j++)
                acc[mt][nt][j] = 0.f;

    // prologue: fill NST-1 stages
    #pragma unroll
    for (int c = 0; c < NST - 1; c++) {
        load_stage(c, c);
        CP_COMMIT();
    }

    // fragment addressing (constant per thread)
    const int arow_l = (lane & 15);
    const int agrp_l = (lane >> 4);
    const int brow_l = (lane & 7) + ((lane >> 4) << 3);
    const int bgrp_l = (lane >> 3) & 1;

    for (int c = 0; c < nk; c++) {
        CP_WAIT(NST - 2);
        __syncthreads();
        if (c + NST - 1 < nk)
            load_stage(c + NST - 1, (c + NST - 1) % NST);
        CP_COMMIT();

        const uint32_t aB = smBase + (c % NST) * STAGE_BYTES;
        const uint32_t bB = aB + A_BYTES;

        #pragma unroll
        for (int ks = 0; ks < 2; ks++) {
            const int agH = ks * 2 + agrp_l;
            const int bgH = ks * 2 + bgrp_l;

            uint32_t bhi[2][4], blo[2][4];
            #pragma unroll
            for (int np = 0; np < 2; np++) {
                const int row = wn + np * 16 + brow_l;
                const uint32_t rb = bB + row * 128;
                ldsm_x4(bhi[np], rb + ((bgH ^ (row & 7)) * 16));
                ldsm_x4(blo[np], rb + (((bgH + 4) ^ (row & 7)) * 16));
            }

            #pragma unroll
            for (int mt = 0; mt < 4; mt++) {
                const int row = wm + mt * 16 + arow_l;
                const uint32_t ra = aB + row * 128;
                uint32_t ahi[4];
                ldsm_x4(ahi, ra + ((agH ^ (row & 7)) * 16));
                #pragma unroll
                for (int nt = 0; nt < 4; nt++) {
                    const int np = nt >> 1, o = (nt & 1) * 2;
                    mma_f16(acc[mt][nt], ahi, bhi[np][o], bhi[np][o + 1]);
                }
                #pragma unroll
                for (int nt = 0; nt < 4; nt++) {
                    const int np = nt >> 1, o = (nt & 1) * 2;
                    mma_f16(acc[mt][nt], ahi, blo[np][o], blo[np][o + 1]);
                }
                if (TERMS == 3) {
                    uint32_t alo[4];
                    ldsm_x4(alo, ra + (((agH + 4) ^ (row & 7)) * 16));
                    #pragma unroll
                    for (int nt = 0; nt < 4; nt++) {
                        const int np = nt >> 1, o = (nt & 1) * 2;
                        mma_f16(acc[mt][nt], alo, bhi[np][o], bhi[np][o + 1]);
                    }
                }
            }
        }
    }

    // ---------------- epilogue ----------------
    const int r0 = lane >> 2;            // 0..7
    const int c0 = (lane & 3) * 2;

    float2 bias2[4];
    if (G1) {
        #pragma unroll
        for (int nt = 0; nt < 4; nt++) {
            const int gc = n0 + wn + nt * 8 + c0;
            bias2[nt].x = bias[gc];
            bias2[nt].y = bias[gc + 1];
        }
    }

    #pragma unroll
    for (int mt = 0; mt < 4; mt++) {
        #pragma unroll
        for (int h = 0; h < 2; h++) {
            const int row = m0 + wm + mt * 16 + h * 8 + r0;
            float* op = outF + (size_t)row * H_ + n0 + wn + c0;
            #pragma unroll
            for (int nt = 0; nt < 4; nt++) {
                float vx = acc[mt][nt][h * 2 + 0];
                float vy = acc[mt][nt][h * 2 + 1];
                if (G1) {
                    vx = fmaxf(vx + bias2[nt].x, 0.f);
                    vy = fmaxf(vy + bias2[nt].y, 0.f);
                }
                *(float2*)(op + nt * 8) = make_float2(vx, vy);
                if (G1) {
                    const size_t off = (size_t)row * H_ + n0 + wn + c0 + nt * 8;
                    *(__half2*)(outHi + off) =
                        __halves2half2(__float2half_rn(vx), __float2half_rn(vy));
                }
            }
        }
    }
}

// ============================================================================
// Local windowed attention — register-tiled (unchanged)
// ============================================================================
#define TS 16
#define KC 128
#define HR (TS + 32)   // 48
#define HPA 132        // hs pitch (float)

__global__ __launch_bounds__(256)
void atten_kernel(const float* __restrict__ h, const float* __restrict__ q,
                  float* __restrict__ out)
{
    __shared__ float hs[HR][HPA];
    __shared__ float sc[TS][AW + 3];

    const int tid = threadIdx.x;
    const int b = blockIdx.y;
    const int s0 = blockIdx.x * TS;

    const float* hB = h + (size_t)b * S_ * H_;
    const float* qB = q + (size_t)b * S_ * H_;
    float*       oB = out + (size_t)b * S_ * H_;

    const int warp = tid >> 5, lane = tid & 31;
    const int lane16 = lane & 15;
    const int sA = warp * 2 + (lane >> 4);
    const int kofs = lane16 * 8;

    // ---------------- Phase A: scores ----------------
    float acc[AW];
    #pragma unroll
    for (int w = 0; w < AW; w++) acc[w] = 0.f;

    for (int kc = 0; kc < H_; kc += KC) {
        __syncthreads();
        for (int i = tid; i < HR * (KC / 4); i += 256) {
            const int r = i >> 5;
            const int c4 = (i & 31) * 4;
            const int g = s0 - 16 + r;
            float4 v = make_float4(0.f, 0.f, 0.f, 0.f);
            if (g >= 0 && g < S_)
                v = *(const float4*)(hB + (size_t)g * H_ + kc + c4);
            *(float4*)&hs[r][c4] = v;
        }
        __syncthreads();

        const float* qp = qB + (size_t)(s0 + sA) * H_ + kc + kofs;
        const float4 qa = *(const float4*)qp;
        const float4 qb = *(const float4*)(qp + 4);

        #pragma unroll
        for (int w = 0; w < AW; w++) {
            const float* hr = &hs[sA + 32 - w][kofs];
            const float4 ha = *(const float4*)hr;
            const float4 hb = *(const float4*)(hr + 4);
            acc[w] += qa.x * ha.x + qa.y * ha.y + qa.z * ha.z + qa.w * ha.w
                    + qb.x * hb.x + qb.y * hb.y + qb.z * hb.z + qb.w * hb.w;
        }
    }

    #pragma unroll
    for (int w = 0; w < AW; w++) {
        #pragma unroll
        for (int d = 8; d >= 1; d >>= 1)
            acc[w] += __shfl_xor_sync(0xffffffffu, acc[w], d);
    }
    #pragma unroll
    for (int w = 0; w < AW; w++) {
        if ((w & 15) == lane16 && (w < 32 || lane16 == 0))
            sc[sA][w] = acc[w] * 0.03125f;
    }
    __syncthreads();

    // ---------------- Phase B: softmax ----------------
    if (tid < TS) {
        float m = -1e30f;
        for (int w = 0; w < AW; w++) m = fmaxf(m, sc[tid][w]);
        float sum = 0.f;
        for (int w = 0; w < AW; w++) {
            const float e = expf(sc[tid][w] - m);
            sc[tid][w] = e;
            sum += e;
        }
        const float inv = 1.f / sum;
        for (int w = 0; w < AW; w++) sc[tid][w] *= inv;
    }

    // ---------------- Phase C: weighted sum ----------------
    const int sg = (tid >> 5) * 2;
    const int kq = (tid & 31) * 4;

    for (int kc = 0; kc < H_; kc += KC) {
        __syncthreads();
        for (int i = tid; i < HR * (KC / 4); i += 256) {
            const int r = i >> 5;
            const int c4 = (i & 31) * 4;
            const int g = s0 - 16 + r;
            float4 v = make_float4(0.f, 0.f, 0.f, 0.f);
            if (g >= 0 && g < S_)
                v = *(const float4*)(hB + (size_t)g * H_ + kc + c4);
            *(float4*)&hs[r][c4] = v;
        }
        __syncthreads();

        float4 a0 = make_float4(0.f, 0.f, 0.f, 0.f);
        float4 a1 = make_float4(0.f, 0.f, 0.f, 0.f);
        #pragma unroll
        for (int j = 0; j < 34; j++) {
            const float4 h4 = *(const float4*)&hs[sg + j][kq];
            if (j <= 32) {
                const float p = sc[sg][32 - j];
                a0.x += p * h4.x; a0.y += p * h4.y;
                a0.z += p * h4.z; a0.w += p * h4.w;
            }
            if (j >= 1) {
                const float p = sc[sg + 1][33 - j];
                a1.x += p * h4.x; a1.y += p * h4.y;
                a1.z += p * h4.z; a1.w += p * h4.w;
            }
        }
        *(float4*)(oB + (size_t)(s0 + sg) * H_ + kc + kq) = a0;
        *(float4*)(oB + (size_t)(s0 + sg + 1) * H_ + kc + kq) = a1;
    }
}

// ============================================================================
// Launch
// ============================================================================
extern "C" void kernel_launch(void* const* d_in, const int* in_sizes, int n_in,
                              void* d_out, int out_size)
{
    const float* x  = (const float*)d_in[0];   // [4,2048,512]
    const float* W1 = (const float*)d_in[1];   // [512,1024]
    const float* b1 = (const float*)d_in[2];   // [1024]
    const float* Wq = (const float*)d_in[3];   // [1024,1024]
    float* out = (float*)d_out;                // [4,2048,1024]

    float *hp, *qp;
    __half *xhi, *xlo, *hhi, *w1thi, *w1tlo, *wqthi, *wqtlo;
    cudaGetSymbolAddress((void**)&hp, g_h);
    cudaGetSymbolAddress((void**)&qp, g_q);
    cudaGetSymbolAddress((void**)&xhi, g_xhi);
    cudaGetSymbolAddress((void**)&xlo, g_xlo);
    cudaGetSymbolAddress((void**)&hhi, g_hhi);
    cudaGetSymbolAddress((void**)&w1thi, g_w1t_hi);
    cudaGetSymbolAddress((void**)&w1tlo, g_w1t_lo);
    cudaGetSymbolAddress((void**)&wqthi, g_wqt_hi);
    cudaGetSymbolAddress((void**)&wqtlo, g_wqt_lo);

    cudaFuncSetAttribute((const void*)hmma_gemm<3, true>,
                         cudaFuncAttributeMaxDynamicSharedMemorySize, GEMM_SMEM);
    cudaFuncSetAttribute((const void*)hmma_gemm<2, false>,
                         cudaFuncAttributeMaxDynamicSharedMemorySize, GEMM_SMEM);

    // Converts
    {
        int n4 = M_ * IN_ / 4;
        split_kernel<<<(n4 + 255) / 256, 256>>>(x, xhi, xlo, n4);
        dim3 t(32, 8);
        transpose_split_kernel<<<dim3(H_ / 32, IN_ / 32), t>>>(W1, w1thi, w1tlo, IN_, H_);
        transpose_split_kernel<<<dim3(H_ / 32, H_ / 32), t>>>(Wq, wqthi, wqtlo, H_, H_);
    }

    // GEMM1: h = relu(x @ W1 + b1), 3-term split (h feeds output directly)
    {
        dim3 grid(H_ / 128, M_ / 256);
        hmma_gemm<3, true><<<grid, 512, GEMM_SMEM>>>(
            xhi, xlo, w1thi, w1tlo, b1, hp, hhi, IN_);
    }
    // GEMM2: q = h @ Wq, 2-term split (q only feeds softmax logits)
    {
        dim3 grid(H_ / 128, M_ / 256);
        hmma_gemm<2, false><<<grid, 512, GEMM_SMEM>>>(
            hhi, nullptr, wqthi, wqtlo, nullptr, qp, nullptr, H_);
    }
    // Attention
    {
        dim3 grid(S_ / TS, B_);
        atten_kernel<<<grid, 256>>>(hp, qp, out);
    }
}

// round 8
// speedup vs baseline: 2.7772x; 1.2720x over previous
#include <cuda_runtime.h>
#include <cuda_fp16.h>
#include <math.h>
#include <stdint.h>

// ============================================================================
// Problem constants
// ============================================================================
#define B_   4
#define S_   2048
#define IN_  512
#define H_   1024
#define M_   (B_ * S_)   // 8192
#define AW   33          // 2*atten_size + 1

// ============================================================================
// Device global scratch (allocation-free per harness rules)
// ============================================================================
__device__ float g_h[(size_t)M_ * H_];
__device__ float g_q[(size_t)M_ * H_];

__device__ __half g_xhi[(size_t)M_ * IN_];
__device__ __half g_hhi[(size_t)M_ * H_];
__device__ __half g_w1t_hi[(size_t)H_ * IN_];   // W1^T [1024,512]
__device__ __half g_w1t_lo[(size_t)H_ * IN_];
__device__ __half g_wqt_hi[(size_t)H_ * H_];    // Wq^T [1024,1024]

// ============================================================================
// PTX helpers (base sm_103 ISA only: cp.async, ldmatrix, mma.sync)
// ============================================================================
__device__ __forceinline__ uint32_t smem_u32(const void* p) {
    uint32_t a;
    asm("{ .reg .u64 t; cvta.to.shared.u64 t, %1; cvt.u32.u64 %0, t; }"
        : "=r"(a) : "l"(p));
    return a;
}

__device__ __forceinline__ void cp_async16(uint32_t dst, const void* src) {
    asm volatile("cp.async.cg.shared.global [%0], [%1], 16;"
                 :: "r"(dst), "l"(src));
}
#define CP_COMMIT() asm volatile("cp.async.commit_group;" ::: "memory")
#define CP_WAIT(n)  asm volatile("cp.async.wait_group %0;" :: "n"(n) : "memory")

__device__ __forceinline__ void ldsm_x4(uint32_t* r, uint32_t addr) {
    asm volatile("ldmatrix.sync.aligned.m8n8.x4.shared.b16 {%0,%1,%2,%3}, [%4];"
                 : "=r"(r[0]), "=r"(r[1]), "=r"(r[2]), "=r"(r[3]) : "r"(addr));
}

__device__ __forceinline__ void mma_f16(float* c, const uint32_t* a,
                                        uint32_t b0, uint32_t b1) {
    asm volatile(
        "mma.sync.aligned.m16n8k16.row.col.f32.f16.f16.f32 "
        "{%0,%1,%2,%3}, {%4,%5,%6,%7}, {%8,%9}, {%0,%1,%2,%3};"
        : "+f"(c[0]), "+f"(c[1]), "+f"(c[2]), "+f"(c[3])
        : "r"(a[0]), "r"(a[1]), "r"(a[2]), "r"(a[3]), "r"(b0), "r"(b1));
}

// ============================================================================
// Convert kernels
// ============================================================================
// fp32 -> fp16 hi only
__global__ void split_hi_kernel(const float* __restrict__ in,
                                __half* __restrict__ hi, int n4) {
    int i = blockIdx.x * blockDim.x + threadIdx.x;
    if (i >= n4) return;
    float4 v = ((const float4*)in)[i];
    ((__half2*)hi)[i * 2 + 0] = __halves2half2(__float2half_rn(v.x),
                                               __float2half_rn(v.y));
    ((__half2*)hi)[i * 2 + 1] = __halves2half2(__float2half_rn(v.z),
                                               __float2half_rn(v.w));
}

// in [R, C] fp32 -> out^T [C, R] half hi (+ lo if WRITE_LO)
template <bool WRITE_LO>
__global__ void transpose_split_kernel(const float* __restrict__ in,
                                       __half* __restrict__ hiT,
                                       __half* __restrict__ loT,
                                       int R, int C) {
    __shared__ float t[32][33];
    const int c0 = blockIdx.x * 32, r0 = blockIdx.y * 32;
    const int tx = threadIdx.x, ty = threadIdx.y;   // 32 x 8
    #pragma unroll
    for (int j = 0; j < 32; j += 8)
        t[ty + j][tx] = in[(size_t)(r0 + ty + j) * C + c0 + tx];
    __syncthreads();
    #pragma unroll
    for (int j = 0; j < 32; j += 8) {
        float v = t[tx][ty + j];
        __half h = __float2half_rn(v);
        size_t o = (size_t)(c0 + ty + j) * R + r0 + tx;
        hiT[o] = h;
        if (WRITE_LO)
            loT[o] = __float2half_rn(v - __half2float(h));
    }
}

// ============================================================================
// HMMA split GEMM: C[M,N] = A[M,K] @ W[K,N], W given transposed [N,K].
// TERMS==1: C = AhiBhi.  TERMS==2: C = Ahi(Bhi+Blo).  TERMS==3: + AloBhi.
// Block tile 256x128, BK=32, 16 warps (warp tile 64x32), 4-stage cp.async.
// SMEM row layout (128B): [hi k0..31 | lo k0..31], 16B groups XOR (row&7).
// ============================================================================
#define NST 4
#define A_BYTES 32768                    // 256 rows x 128B
#define STAGE_BYTES (A_BYTES + 16384)    // + B: 128 rows x 128B
#define GEMM_SMEM (NST * STAGE_BYTES)    // 192 KB

template <int TERMS, bool G1>
__global__ __launch_bounds__(512, 1)
void hmma_gemm(const __half* __restrict__ Ahi, const __half* __restrict__ Alo,
               const __half* __restrict__ Bhi, const __half* __restrict__ Blo,
               const float* __restrict__ bias,
               float* __restrict__ outF,
               __half* __restrict__ outHi,
               int K)
{
    extern __shared__ __align__(1024) char smem[];
    const uint32_t smBase = smem_u32(smem);

    const int tid  = threadIdx.x;
    const int wid  = tid >> 5;
    const int lane = tid & 31;
    const int m0 = blockIdx.y * 256;
    const int n0 = blockIdx.x * 128;
    const int nk = K / 32;

    const int wm = (wid & 3) * 64;    // warp m offset within block
    const int wn = (wid >> 2) * 32;   // warp n offset within block

    // --- loader mapping ---
    const int half_sel = tid & 1;             // 0 -> hi, 1 -> lo
    const int arow = tid >> 1;                // 0..255
    const bool loadA = (TERMS == 3) || (half_sel == 0);
    const bool loadB = (tid < 256) && ((TERMS >= 2) || (half_sel == 0));
    const int brow = (tid >> 1) & 127;
    const __half* srcA = ((TERMS == 3 && half_sel) ? Alo : Ahi)
                         + (size_t)(m0 + arow) * K;
    const __half* srcB = ((TERMS >= 2 && half_sel) ? Blo : Bhi)
                         + (size_t)(n0 + brow) * K;
    uint32_t dstA[4], dstB[4];
    #pragma unroll
    for (int g = 0; g < 4; g++) {
        const int lg = half_sel * 4 + g;
        dstA[g] = smBase + arow * 128 + ((lg ^ (arow & 7)) * 16);
        dstB[g] = smBase + A_BYTES + brow * 128 + ((lg ^ (brow & 7)) * 16);
    }

    auto load_stage = [&](int c, int s) {
        const uint32_t so = s * STAGE_BYTES;
        if (loadA) {
            const __half* sa = srcA + c * 32;
            #pragma unroll
            for (int g = 0; g < 4; g++)
                cp_async16(dstA[g] + so, sa + g * 8);
        }
        if (loadB) {
            const __half* sb = srcB + c * 32;
            #pragma unroll
            for (int g = 0; g < 4; g++)
                cp_async16(dstB[g] + so, sb + g * 8);
        }
    };

    float acc[4][4][4];
    #pragma unroll
    for (int mt = 0; mt < 4; mt++)
        #pragma unroll
        for (int nt = 0; nt < 4; nt++)
            #pragma unroll
            for (int j = 0; j < 4; j++)
                acc[mt][nt][j] = 0.f;

    // prologue: fill NST-1 stages
    #pragma unroll
    for (int c = 0; c < NST - 1; c++) {
        load_stage(c, c);
        CP_COMMIT();
    }

    // fragment addressing (constant per thread)
    const int arow_l = (lane & 15);
    const int agrp_l = (lane >> 4);
    const int brow_l = (lane & 7) + ((lane >> 4) << 3);
    const int bgrp_l = (lane >> 3) & 1;

    for (int c = 0; c < nk; c++) {
        CP_WAIT(NST - 2);
        __syncthreads();
        if (c + NST - 1 < nk)
            load_stage(c + NST - 1, (c + NST - 1) % NST);
        CP_COMMIT();

        const uint32_t aB = smBase + (c % NST) * STAGE_BYTES;
        const uint32_t bB = aB + A_BYTES;

        #pragma unroll
        for (int ks = 0; ks < 2; ks++) {
            const int agH = ks * 2 + agrp_l;
            const int bgH = ks * 2 + bgrp_l;

            uint32_t bhi[2][4], blo[2][4];
            #pragma unroll
            for (int np = 0; np < 2; np++) {
                const int row = wn + np * 16 + brow_l;
                const uint32_t rb = bB + row * 128;
                ldsm_x4(bhi[np], rb + ((bgH ^ (row & 7)) * 16));
                if (TERMS >= 2)
                    ldsm_x4(blo[np], rb + (((bgH + 4) ^ (row & 7)) * 16));
            }

            #pragma unroll
            for (int mt = 0; mt < 4; mt++) {
                const int row = wm + mt * 16 + arow_l;
                const uint32_t ra = aB + row * 128;
                uint32_t ahi[4];
                ldsm_x4(ahi, ra + ((agH ^ (row & 7)) * 16));
                #pragma unroll
                for (int nt = 0; nt < 4; nt++) {
                    const int np = nt >> 1, o = (nt & 1) * 2;
                    mma_f16(acc[mt][nt], ahi, bhi[np][o], bhi[np][o + 1]);
                }
                if (TERMS >= 2) {
                    #pragma unroll
                    for (int nt = 0; nt < 4; nt++) {
                        const int np = nt >> 1, o = (nt & 1) * 2;
                        mma_f16(acc[mt][nt], ahi, blo[np][o], blo[np][o + 1]);
                    }
                }
                if (TERMS == 3) {
                    uint32_t alo[4];
                    ldsm_x4(alo, ra + (((agH + 4) ^ (row & 7)) * 16));
                    #pragma unroll
                    for (int nt = 0; nt < 4; nt++) {
                        const int np = nt >> 1, o = (nt & 1) * 2;
                        mma_f16(acc[mt][nt], alo, bhi[np][o], bhi[np][o + 1]);
                    }
                }
            }
        }
    }

    // ---------------- epilogue ----------------
    const int r0 = lane >> 2;            // 0..7
    const int c0 = (lane & 3) * 2;

    float2 bias2[4];
    if (G1) {
        #pragma unroll
        for (int nt = 0; nt < 4; nt++) {
            const int gc = n0 + wn + nt * 8 + c0;
            bias2[nt].x = bias[gc];
            bias2[nt].y = bias[gc + 1];
        }
    }

    #pragma unroll
    for (int mt = 0; mt < 4; mt++) {
        #pragma unroll
        for (int h = 0; h < 2; h++) {
            const int row = m0 + wm + mt * 16 + h * 8 + r0;
            float* op = outF + (size_t)row * H_ + n0 + wn + c0;
            #pragma unroll
            for (int nt = 0; nt < 4; nt++) {
                float vx = acc[mt][nt][h * 2 + 0];
                float vy = acc[mt][nt][h * 2 + 1];
                if (G1) {
                    vx = fmaxf(vx + bias2[nt].x, 0.f);
                    vy = fmaxf(vy + bias2[nt].y, 0.f);
                }
                *(float2*)(op + nt * 8) = make_float2(vx, vy);
                if (G1) {
                    const size_t off = (size_t)row * H_ + n0 + wn + c0 + nt * 8;
                    *(__half2*)(outHi + off) =
                        __halves2half2(__float2half_rn(vx), __float2half_rn(vy));
                }
            }
        }
    }
}

// ============================================================================
// Local windowed attention — register-tiled (unchanged)
// ============================================================================
#define TS 16
#define KC 128
#define HR (TS + 32)   // 48
#define HPA 132        // hs pitch (float)

__global__ __launch_bounds__(256)
void atten_kernel(const float* __restrict__ h, const float* __restrict__ q,
                  float* __restrict__ out)
{
    __shared__ float hs[HR][HPA];
    __shared__ float sc[TS][AW + 3];

    const int tid = threadIdx.x;
    const int b = blockIdx.y;
    const int s0 = blockIdx.x * TS;

    const float* hB = h + (size_t)b * S_ * H_;
    const float* qB = q + (size_t)b * S_ * H_;
    float*       oB = out + (size_t)b * S_ * H_;

    const int warp = tid >> 5, lane = tid & 31;
    const int lane16 = lane & 15;
    const int sA = warp * 2 + (lane >> 4);
    const int kofs = lane16 * 8;

    // ---------------- Phase A: scores ----------------
    float acc[AW];
    #pragma unroll
    for (int w = 0; w < AW; w++) acc[w] = 0.f;

    for (int kc = 0; kc < H_; kc += KC) {
        __syncthreads();
        for (int i = tid; i < HR * (KC / 4); i += 256) {
            const int r = i >> 5;
            const int c4 = (i & 31) * 4;
            const int g = s0 - 16 + r;
            float4 v = make_float4(0.f, 0.f, 0.f, 0.f);
            if (g >= 0 && g < S_)
                v = *(const float4*)(hB + (size_t)g * H_ + kc + c4);
            *(float4*)&hs[r][c4] = v;
        }
        __syncthreads();

        const float* qp = qB + (size_t)(s0 + sA) * H_ + kc + kofs;
        const float4 qa = *(const float4*)qp;
        const float4 qb = *(const float4*)(qp + 4);

        #pragma unroll
        for (int w = 0; w < AW; w++) {
            const float* hr = &hs[sA + 32 - w][kofs];
            const float4 ha = *(const float4*)hr;
            const float4 hb = *(const float4*)(hr + 4);
            acc[w] += qa.x * ha.x + qa.y * ha.y + qa.z * ha.z + qa.w * ha.w
                    + qb.x * hb.x + qb.y * hb.y + qb.z * hb.z + qb.w * hb.w;
        }
    }

    #pragma unroll
    for (int w = 0; w < AW; w++) {
        #pragma unroll
        for (int d = 8; d >= 1; d >>= 1)
            acc[w] += __shfl_xor_sync(0xffffffffu, acc[w], d);
    }
    #pragma unroll
    for (int w = 0; w < AW; w++) {
        if ((w & 15) == lane16 && (w < 32 || lane16 == 0))
            sc[sA][w] = acc[w] * 0.03125f;
    }
    __syncthreads();

    // ---------------- Phase B: softmax ----------------
    if (tid < TS) {
        float m = -1e30f;
        for (int w = 0; w < AW; w++) m = fmaxf(m, sc[tid][w]);
        float sum = 0.f;
        for (int w = 0; w < AW; w++) {
            const float e = expf(sc[tid][w] - m);
            sc[tid][w] = e;
            sum += e;
        }
        const float inv = 1.f / sum;
        for (int w = 0; w < AW; w++) sc[tid][w] *= inv;
    }

    // ---------------- Phase C: weighted sum ----------------
    const int sg = (tid >> 5) * 2;
    const int kq = (tid & 31) * 4;

    for (int kc = 0; kc < H_; kc += KC) {
        __syncthreads();
        for (int i = tid; i < HR * (KC / 4); i += 256) {
            const int r = i >> 5;
            const int c4 = (i & 31) * 4;
            const int g = s0 - 16 + r;
            float4 v = make_float4(0.f, 0.f, 0.f, 0.f);
            if (g >= 0 && g < S_)
                v = *(const float4*)(hB + (size_t)g * H_ + kc + c4);
            *(float4*)&hs[r][c4] = v;
        }
        __syncthreads();

        float4 a0 = make_float4(0.f, 0.f, 0.f, 0.f);
        float4 a1 = make_float4(0.f, 0.f, 0.f, 0.f);
        #pragma unroll
        for (int j = 0; j < 34; j++) {
            const float4 h4 = *(const float4*)&hs[sg + j][kq];
            if (j <= 32) {
                const float p = sc[sg][32 - j];
                a0.x += p * h4.x; a0.y += p * h4.y;
                a0.z += p * h4.z; a0.w += p * h4.w;
            }
            if (j >= 1) {
                const float p = sc[sg + 1][33 - j];
                a1.x += p * h4.x; a1.y += p * h4.y;
                a1.z += p * h4.z; a1.w += p * h4.w;
            }
        }
        *(float4*)(oB + (size_t)(s0 + sg) * H_ + kc + kq) = a0;
        *(float4*)(oB + (size_t)(s0 + sg + 1) * H_ + kc + kq) = a1;
    }
}

// ============================================================================
// Launch
// ============================================================================
extern "C" void kernel_launch(void* const* d_in, const int* in_sizes, int n_in,
                              void* d_out, int out_size)
{
    const float* x  = (const float*)d_in[0];   // [4,2048,512]
    const float* W1 = (const float*)d_in[1];   // [512,1024]
    const float* b1 = (const float*)d_in[2];   // [1024]
    const float* Wq = (const float*)d_in[3];   // [1024,1024]
    float* out = (float*)d_out;                // [4,2048,1024]

    float *hp, *qp;
    __half *xhi, *hhi, *w1thi, *w1tlo, *wqthi;
    cudaGetSymbolAddress((void**)&hp, g_h);
    cudaGetSymbolAddress((void**)&qp, g_q);
    cudaGetSymbolAddress((void**)&xhi, g_xhi);
    cudaGetSymbolAddress((void**)&hhi, g_hhi);
    cudaGetSymbolAddress((void**)&w1thi, g_w1t_hi);
    cudaGetSymbolAddress((void**)&w1tlo, g_w1t_lo);
    cudaGetSymbolAddress((void**)&wqthi, g_wqt_hi);

    cudaFuncSetAttribute((const void*)hmma_gemm<2, true>,
                         cudaFuncAttributeMaxDynamicSharedMemorySize, GEMM_SMEM);
    cudaFuncSetAttribute((const void*)hmma_gemm<1, false>,
                         cudaFuncAttributeMaxDynamicSharedMemorySize, GEMM_SMEM);

    // Converts
    {
        int n4 = M_ * IN_ / 4;
        split_hi_kernel<<<(n4 + 255) / 256, 256>>>(x, xhi, n4);
        dim3 t(32, 8);
        transpose_split_kernel<true><<<dim3(H_ / 32, IN_ / 32), t>>>(
            W1, w1thi, w1tlo, IN_, H_);
        transpose_split_kernel<false><<<dim3(H_ / 32, H_ / 32), t>>>(
            Wq, wqthi, nullptr, H_, H_);
    }

    // GEMM1: h = relu(xhi @ (W1hi + W1lo) + b1)   (2-term)
    {
        dim3 grid(H_ / 128, M_ / 256);
        hmma_gemm<2, true><<<grid, 512, GEMM_SMEM>>>(
            xhi, nullptr, w1thi, w1tlo, b1, hp, hhi, IN_);
    }
    // GEMM2: q = hhi @ Wqhi   (1-term; error only perturbs softmax logits)
    {
        dim3 grid(H_ / 128, M_ / 256);
        hmma_gemm<1, false><<<grid, 512, GEMM_SMEM>>>(
            hhi, nullptr, wqthi, nullptr, nullptr, qp, nullptr, H_);
    }
    // Attention
    {
        dim3 grid(S_ / TS, B_);
        atten_kernel<<<grid, 256>>>(hp, qp, out);
    }
}

// round 9
// speedup vs baseline: 3.5006x; 1.2605x over previous
#include <cuda_runtime.h>
#include <cuda_fp16.h>
#include <math.h>
#include <stdint.h>

// ============================================================================
// Problem constants
// ============================================================================
#define B_   4
#define S_   2048
#define IN_  512
#define H_   1024
#define M_   (B_ * S_)   // 8192
#define AW   33          // 2*atten_size + 1

// ============================================================================
// Device global scratch (allocation-free per harness rules)
// ============================================================================
__device__ __half g_xhi[(size_t)M_ * IN_];
__device__ __half g_hhi[(size_t)M_ * H_];
__device__ __half g_qhi[(size_t)M_ * H_];
__device__ __half g_w1t_hi[(size_t)H_ * IN_];   // W1^T [1024,512]
__device__ __half g_w1t_lo[(size_t)H_ * IN_];
__device__ __half g_wqt_hi[(size_t)H_ * H_];    // Wq^T [1024,1024]

// ============================================================================
// PTX helpers (base sm_103 ISA only: cp.async, ldmatrix, mma.sync)
// ============================================================================
__device__ __forceinline__ uint32_t smem_u32(const void* p) {
    uint32_t a;
    asm("{ .reg .u64 t; cvta.to.shared.u64 t, %1; cvt.u32.u64 %0, t; }"
        : "=r"(a) : "l"(p));
    return a;
}

__device__ __forceinline__ void cp_async16(uint32_t dst, const void* src) {
    asm volatile("cp.async.cg.shared.global [%0], [%1], 16;"
                 :: "r"(dst), "l"(src));
}
#define CP_COMMIT() asm volatile("cp.async.commit_group;" ::: "memory")
#define CP_WAIT(n)  asm volatile("cp.async.wait_group %0;" :: "n"(n) : "memory")

__device__ __forceinline__ void ldsm_x4(uint32_t* r, uint32_t addr) {
    asm volatile("ldmatrix.sync.aligned.m8n8.x4.shared.b16 {%0,%1,%2,%3}, [%4];"
                 : "=r"(r[0]), "=r"(r[1]), "=r"(r[2]), "=r"(r[3]) : "r"(addr));
}

__device__ __forceinline__ void mma_f16(float* c, const uint32_t* a,
                                        uint32_t b0, uint32_t b1) {
    asm volatile(
        "mma.sync.aligned.m16n8k16.row.col.f32.f16.f16.f32 "
        "{%0,%1,%2,%3}, {%4,%5,%6,%7}, {%8,%9}, {%0,%1,%2,%3};"
        : "+f"(c[0]), "+f"(c[1]), "+f"(c[2]), "+f"(c[3])
        : "r"(a[0]), "r"(a[1]), "r"(a[2]), "r"(a[3]), "r"(b0), "r"(b1));
}

// unpack 8 halves (uint4) -> 8 floats
__device__ __forceinline__ void h8_to_f8(uint4 v, float* f) {
    union { uint32_t u; __half2 h; } c;
    c.u = v.x; float2 t0 = __half22float2(c.h);
    c.u = v.y; float2 t1 = __half22float2(c.h);
    c.u = v.z; float2 t2 = __half22float2(c.h);
    c.u = v.w; float2 t3 = __half22float2(c.h);
    f[0] = t0.x; f[1] = t0.y; f[2] = t1.x; f[3] = t1.y;
    f[4] = t2.x; f[5] = t2.y; f[6] = t3.x; f[7] = t3.y;
}

// ============================================================================
// Convert kernels
// ============================================================================
__global__ void split_hi_kernel(const float* __restrict__ in,
                                __half* __restrict__ hi, int n4) {
    int i = blockIdx.x * blockDim.x + threadIdx.x;
    if (i >= n4) return;
    float4 v = ((const float4*)in)[i];
    ((__half2*)hi)[i * 2 + 0] = __halves2half2(__float2half_rn(v.x),
                                               __float2half_rn(v.y));
    ((__half2*)hi)[i * 2 + 1] = __halves2half2(__float2half_rn(v.z),
                                               __float2half_rn(v.w));
}

template <bool WRITE_LO>
__global__ void transpose_split_kernel(const float* __restrict__ in,
                                       __half* __restrict__ hiT,
                                       __half* __restrict__ loT,
                                       int R, int C) {
    __shared__ float t[32][33];
    const int c0 = blockIdx.x * 32, r0 = blockIdx.y * 32;
    const int tx = threadIdx.x, ty = threadIdx.y;   // 32 x 8
    #pragma unroll
    for (int j = 0; j < 32; j += 8)
        t[ty + j][tx] = in[(size_t)(r0 + ty + j) * C + c0 + tx];
    __syncthreads();
    #pragma unroll
    for (int j = 0; j < 32; j += 8) {
        float v = t[tx][ty + j];
        __half h = __float2half_rn(v);
        size_t o = (size_t)(c0 + ty + j) * R + r0 + tx;
        hiT[o] = h;
        if (WRITE_LO)
            loT[o] = __float2half_rn(v - __half2float(h));
    }
}

// ============================================================================
// HMMA split GEMM: C[M,N] = A[M,K] @ W[K,N], W transposed [N,K].
// TERMS==1: C = A·Bhi.  TERMS==2: C = A·(Bhi+Blo).
// Block tile 256x128, BK=32, 16 warps (warp tile 64x32), 4-stage cp.async.
// Output: fp16 only (optionally bias+relu first).
// ============================================================================
#define NST 4
#define A_BYTES 32768                    // 256 rows x 128B
#define STAGE_BYTES (A_BYTES + 16384)    // + B: 128 rows x 128B
#define GEMM_SMEM (NST * STAGE_BYTES)    // 192 KB

template <int TERMS, bool RELU_BIAS>
__global__ __launch_bounds__(512, 1)
void hmma_gemm(const __half* __restrict__ Ahi,
               const __half* __restrict__ Bhi, const __half* __restrict__ Blo,
               const float* __restrict__ bias,
               __half* __restrict__ outHi,
               int K)
{
    extern __shared__ __align__(1024) char smem[];
    const uint32_t smBase = smem_u32(smem);

    const int tid  = threadIdx.x;
    const int wid  = tid >> 5;
    const int lane = tid & 31;
    const int m0 = blockIdx.y * 256;
    const int n0 = blockIdx.x * 128;
    const int nk = K / 32;

    const int wm = (wid & 3) * 64;
    const int wn = (wid >> 2) * 32;

    // --- loader mapping ---
    const int half_sel = tid & 1;
    const int arow = tid >> 1;                // 0..255
    const bool loadA = (half_sel == 0);       // A always 1-term now
    const bool loadB = (tid < 256) && ((TERMS >= 2) || (half_sel == 0));
    const int brow = (tid >> 1) & 127;
    const __half* srcA = Ahi + (size_t)(m0 + arow) * K;
    const __half* srcB = ((TERMS >= 2 && half_sel) ? Blo : Bhi)
                         + (size_t)(n0 + brow) * K;
    uint32_t dstA[4], dstB[4];
    #pragma unroll
    for (int g = 0; g < 4; g++) {
        const int lg = half_sel * 4 + g;
        dstA[g] = smBase + arow * 128 + (((0 * 4 + g) ^ (arow & 7)) * 16);
        dstB[g] = smBase + A_BYTES + brow * 128 + ((lg ^ (brow & 7)) * 16);
    }

    auto load_stage = [&](int c, int s) {
        const uint32_t so = s * STAGE_BYTES;
        if (loadA) {
            const __half* sa = srcA + c * 32;
            #pragma unroll
            for (int g = 0; g < 4; g++)
                cp_async16(dstA[g] + so, sa + g * 8);
        }
        if (loadB) {
            const __half* sb = srcB + c * 32;
            #pragma unroll
            for (int g = 0; g < 4; g++)
                cp_async16(dstB[g] + so, sb + g * 8);
        }
    };

    float acc[4][4][4];
    #pragma unroll
    for (int mt = 0; mt < 4; mt++)
        #pragma unroll
        for (int nt = 0; nt < 4; nt++)
            #pragma unroll
            for (int j = 0; j < 4; j++)
                acc[mt][nt][j] = 0.f;

    #pragma unroll
    for (int c = 0; c < NST - 1; c++) {
        load_stage(c, c);
        CP_COMMIT();
    }

    const int arow_l = (lane & 15);
    const int agrp_l = (lane >> 4);
    const int brow_l = (lane & 7) + ((lane >> 4) << 3);
    const int bgrp_l = (lane >> 3) & 1;

    for (int c = 0; c < nk; c++) {
        CP_WAIT(NST - 2);
        __syncthreads();
        if (c + NST - 1 < nk)
            load_stage(c + NST - 1, (c + NST - 1) % NST);
        CP_COMMIT();

        const uint32_t aB = smBase + (c % NST) * STAGE_BYTES;
        const uint32_t bB = aB + A_BYTES;

        #pragma unroll
        for (int ks = 0; ks < 2; ks++) {
            const int agH = ks * 2 + agrp_l;
            const int bgH = ks * 2 + bgrp_l;

            uint32_t bhi[2][4], blo[2][4];
            #pragma unroll
            for (int np = 0; np < 2; np++) {
                const int row = wn + np * 16 + brow_l;
                const uint32_t rb = bB + row * 128;
                ldsm_x4(bhi[np], rb + ((bgH ^ (row & 7)) * 16));
                if (TERMS >= 2)
                    ldsm_x4(blo[np], rb + (((bgH + 4) ^ (row & 7)) * 16));
            }

            #pragma unroll
            for (int mt = 0; mt < 4; mt++) {
                const int row = wm + mt * 16 + arow_l;
                const uint32_t ra = aB + row * 128;
                uint32_t ahi[4];
                ldsm_x4(ahi, ra + ((agH ^ (row & 7)) * 16));
                #pragma unroll
                for (int nt = 0; nt < 4; nt++) {
                    const int np = nt >> 1, o = (nt & 1) * 2;
                    mma_f16(acc[mt][nt], ahi, bhi[np][o], bhi[np][o + 1]);
                }
                if (TERMS >= 2) {
                    #pragma unroll
                    for (int nt = 0; nt < 4; nt++) {
                        const int np = nt >> 1, o = (nt & 1) * 2;
                        mma_f16(acc[mt][nt], ahi, blo[np][o], blo[np][o + 1]);
                    }
                }
            }
        }
    }

    // ---------------- epilogue: fp16 only ----------------
    const int r0 = lane >> 2;
    const int c0 = (lane & 3) * 2;

    float2 bias2[4];
    if (RELU_BIAS) {
        #pragma unroll
        for (int nt = 0; nt < 4; nt++) {
            const int gc = n0 + wn + nt * 8 + c0;
            bias2[nt].x = bias[gc];
            bias2[nt].y = bias[gc + 1];
        }
    }

    #pragma unroll
    for (int mt = 0; mt < 4; mt++) {
        #pragma unroll
        for (int h = 0; h < 2; h++) {
            const int row = m0 + wm + mt * 16 + h * 8 + r0;
            __half* op = outHi + (size_t)row * H_ + n0 + wn + c0;
            #pragma unroll
            for (int nt = 0; nt < 4; nt++) {
                float vx = acc[mt][nt][h * 2 + 0];
                float vy = acc[mt][nt][h * 2 + 1];
                if (RELU_BIAS) {
                    vx = fmaxf(vx + bias2[nt].x, 0.f);
                    vy = fmaxf(vy + bias2[nt].y, 0.f);
                }
                *(__half2*)(op + nt * 8) =
                    __halves2half2(__float2half_rn(vx), __float2half_rn(vy));
            }
        }
    }
}

// ============================================================================
// Local windowed attention — fp16 resident neighborhood, single load.
// Block: (batch, 16 s). smem: hs[48][1032] fp16 (~97KB) + sc[16][36] fp32.
// Phase A: thread (s, 8-col slice), q fp16 from gmem, 33 fp32 accs, shfl.
// Phase C: thread (2 s-rows, 8 cols, 4 of 8 chunks), shared h loads.
// ============================================================================
#define TS 16
#define HPH 1032   // row pitch in halves (2064 B)
#define ATT_SMEM (48 * HPH * 2 + TS * 36 * 4)

__global__ __launch_bounds__(256, 2)
void atten_kernel(const __half* __restrict__ hh, const __half* __restrict__ qh,
                  float* __restrict__ out)
{
    extern __shared__ __align__(16) char asmem[];
    __half* hs = (__half*)asmem;                       // [48][HPH]
    float (*sc)[36] = (float(*)[36])(asmem + 48 * HPH * 2);

    const int tid = threadIdx.x;
    const int b = blockIdx.y;
    const int s0 = blockIdx.x * TS;

    const __half* hB = hh + (size_t)b * S_ * H_;
    const __half* qB = qh + (size_t)b * S_ * H_;
    float*        oB = out + (size_t)b * S_ * H_;

    // ---- load 48 x 1024 fp16 neighborhood once ----
    for (int i = tid; i < 48 * 128; i += 256) {
        const int r = i >> 7;
        const int c = (i & 127) * 8;
        const int g = s0 - 16 + r;
        uint4 v = make_uint4(0, 0, 0, 0);
        if (g >= 0 && g < S_)
            v = *(const uint4*)(hB + (size_t)g * H_ + c);
        *(uint4*)&hs[r * HPH + c] = v;
    }
    __syncthreads();

    // ---------------- Phase A: scores ----------------
    const int warp = tid >> 5, lane = tid & 31;
    const int lane16 = lane & 15;
    const int sA = warp * 2 + (lane >> 4);   // 0..15
    const int kofs = lane16 * 8;

    float acc[AW];
    #pragma unroll
    for (int w = 0; w < AW; w++) acc[w] = 0.f;

    for (int kc = 0; kc < H_; kc += 128) {
        float qv[8];
        h8_to_f8(*(const uint4*)(qB + (size_t)(s0 + sA) * H_ + kc + kofs), qv);

        #pragma unroll
        for (int w = 0; w < AW; w++) {
            float hv[8];
            h8_to_f8(*(const uint4*)&hs[(sA + 32 - w) * HPH + kc + kofs], hv);
            float s = acc[w];
            #pragma unroll
            for (int k = 0; k < 8; k++) s += qv[k] * hv[k];
            acc[w] = s;
        }
    }

    #pragma unroll
    for (int w = 0; w < AW; w++) {
        #pragma unroll
        for (int d = 8; d >= 1; d >>= 1)
            acc[w] += __shfl_xor_sync(0xffffffffu, acc[w], d);
    }
    #pragma unroll
    for (int w = 0; w < AW; w++) {
        if ((w & 15) == lane16 && (w < 32 || lane16 == 0))
            sc[sA][w] = acc[w] * 0.03125f;   // 1/sqrt(1024)
    }
    __syncthreads();

    // ---------------- Phase B: softmax ----------------
    if (tid < TS) {
        float m = -1e30f;
        for (int w = 0; w < AW; w++) m = fmaxf(m, sc[tid][w]);
        float sum = 0.f;
        for (int w = 0; w < AW; w++) {
            const float e = expf(sc[tid][w] - m);
            sc[tid][w] = e;
            sum += e;
        }
        const float inv = 1.f / sum;
        for (int w = 0; w < AW; w++) sc[tid][w] *= inv;
    }
    __syncthreads();

    // ---------------- Phase C: weighted sum ----------------
    // thread: s-pair sp (8), col-group cg (16 x 8 cols), chunk-half hsel (2)
    const int sg = ((tid >> 4) & 7) * 2;
    const int cg = (tid & 15) * 8;
    const int hsel = tid >> 7;

    for (int ci = 0; ci < 4; ci++) {
        const int kc = (hsel * 4 + ci) * 128;
        float a0[8], a1[8];
        #pragma unroll
        for (int k = 0; k < 8; k++) { a0[k] = 0.f; a1[k] = 0.f; }

        #pragma unroll
        for (int j = 0; j < 34; j++) {
            float hv[8];
            h8_to_f8(*(const uint4*)&hs[(sg + j) * HPH + kc + cg], hv);
            if (j <= 32) {
                const float p = sc[sg][32 - j];
                #pragma unroll
                for (int k = 0; k < 8; k++) a0[k] += p * hv[k];
            }
            if (j >= 1) {
                const float p = sc[sg + 1][33 - j];
                #pragma unroll
                for (int k = 0; k < 8; k++) a1[k] += p * hv[k];
            }
        }
        float* o0 = oB + (size_t)(s0 + sg) * H_ + kc + cg;
        float* o1 = oB + (size_t)(s0 + sg + 1) * H_ + kc + cg;
        *(float4*)(o0)     = make_float4(a0[0], a0[1], a0[2], a0[3]);
        *(float4*)(o0 + 4) = make_float4(a0[4], a0[5], a0[6], a0[7]);
        *(float4*)(o1)     = make_float4(a1[0], a1[1], a1[2], a1[3]);
        *(float4*)(o1 + 4) = make_float4(a1[4], a1[5], a1[6], a1[7]);
    }
}

// ============================================================================
// Launch
// ============================================================================
extern "C" void kernel_launch(void* const* d_in, const int* in_sizes, int n_in,
                              void* d_out, int out_size)
{
    const float* x  = (const float*)d_in[0];   // [4,2048,512]
    const float* W1 = (const float*)d_in[1];   // [512,1024]
    const float* b1 = (const float*)d_in[2];   // [1024]
    const float* Wq = (const float*)d_in[3];   // [1024,1024]
    float* out = (float*)d_out;                // [4,2048,1024]

    __half *xhi, *hhi, *qhi, *w1thi, *w1tlo, *wqthi;
    cudaGetSymbolAddress((void**)&xhi, g_xhi);
    cudaGetSymbolAddress((void**)&hhi, g_hhi);
    cudaGetSymbolAddress((void**)&qhi, g_qhi);
    cudaGetSymbolAddress((void**)&w1thi, g_w1t_hi);
    cudaGetSymbolAddress((void**)&w1tlo, g_w1t_lo);
    cudaGetSymbolAddress((void**)&wqthi, g_wqt_hi);

    cudaFuncSetAttribute((const void*)hmma_gemm<2, true>,
                         cudaFuncAttributeMaxDynamicSharedMemorySize, GEMM_SMEM);
    cudaFuncSetAttribute((const void*)hmma_gemm<1, false>,
                         cudaFuncAttributeMaxDynamicSharedMemorySize, GEMM_SMEM);
    cudaFuncSetAttribute((const void*)atten_kernel,
                         cudaFuncAttributeMaxDynamicSharedMemorySize, ATT_SMEM);

    // Converts
    {
        int n4 = M_ * IN_ / 4;
        split_hi_kernel<<<(n4 + 255) / 256, 256>>>(x, xhi, n4);
        dim3 t(32, 8);
        transpose_split_kernel<true><<<dim3(H_ / 32, IN_ / 32), t>>>(
            W1, w1thi, w1tlo, IN_, H_);
        transpose_split_kernel<false><<<dim3(H_ / 32, H_ / 32), t>>>(
            Wq, wqthi, nullptr, H_, H_);
    }

    // GEMM1: hhi = fp16(relu(xhi @ (W1hi + W1lo) + b1))
    {
        dim3 grid(H_ / 128, M_ / 256);
        hmma_gemm<2, true><<<grid, 512, GEMM_SMEM>>>(
            xhi, w1thi, w1tlo, b1, hhi, IN_);
    }
    // GEMM2: qhi = fp16(hhi @ Wqhi)
    {
        dim3 grid(H_ / 128, M_ / 256);
        hmma_gemm<1, false><<<grid, 512, GEMM_SMEM>>>(
            hhi, wqthi, nullptr, nullptr, qhi, H_);
    }
    // Attention
    {
        dim3 grid(S_ / TS, B_);
        atten_kernel<<<grid, 256, ATT_SMEM>>>(hhi, qhi, out);
    }
}

// round 10
// speedup vs baseline: 4.6556x; 1.3299x over previous
#include <cuda_runtime.h>
#include <cuda_fp16.h>
#include <math.h>
#include <stdint.h>

// ============================================================================
// Problem constants
// ============================================================================
#define B_   4
#define S_   2048
#define IN_  512
#define H_   1024
#define M_   (B_ * S_)   // 8192
#define AW   33          // 2*atten_size + 1

// ============================================================================
// Device global scratch (allocation-free per harness rules)
// ============================================================================
__device__ __half g_xhi[(size_t)M_ * IN_];
__device__ __half g_hhi[(size_t)M_ * H_];
__device__ __half g_qhi[(size_t)M_ * H_];
__device__ __half g_w1t_hi[(size_t)H_ * IN_];   // W1^T [1024,512]
__device__ __half g_wqt_hi[(size_t)H_ * H_];    // Wq^T [1024,1024]

// ============================================================================
// PTX helpers (base sm_103 ISA only: cp.async, ldmatrix, mma.sync)
// ============================================================================
__device__ __forceinline__ uint32_t smem_u32(const void* p) {
    uint32_t a;
    asm("{ .reg .u64 t; cvta.to.shared.u64 t, %1; cvt.u32.u64 %0, t; }"
        : "=r"(a) : "l"(p));
    return a;
}

__device__ __forceinline__ void cp_async16(uint32_t dst, const void* src) {
    asm volatile("cp.async.cg.shared.global [%0], [%1], 16;"
                 :: "r"(dst), "l"(src));
}
#define CP_COMMIT() asm volatile("cp.async.commit_group;" ::: "memory")
#define CP_WAIT(n)  asm volatile("cp.async.wait_group %0;" :: "n"(n) : "memory")

__device__ __forceinline__ void ldsm_x4(uint32_t* r, uint32_t addr) {
    asm volatile("ldmatrix.sync.aligned.m8n8.x4.shared.b16 {%0,%1,%2,%3}, [%4];"
                 : "=r"(r[0]), "=r"(r[1]), "=r"(r[2]), "=r"(r[3]) : "r"(addr));
}

__device__ __forceinline__ void mma_f16(float* c, const uint32_t* a,
                                        uint32_t b0, uint32_t b1) {
    asm volatile(
        "mma.sync.aligned.m16n8k16.row.col.f32.f16.f16.f32 "
        "{%0,%1,%2,%3}, {%4,%5,%6,%7}, {%8,%9}, {%0,%1,%2,%3};"
        : "+f"(c[0]), "+f"(c[1]), "+f"(c[2]), "+f"(c[3])
        : "r"(a[0]), "r"(a[1]), "r"(a[2]), "r"(a[3]), "r"(b0), "r"(b1));
}

// unpack 8 halves (uint4) -> 8 floats
__device__ __forceinline__ void h8_to_f8(uint4 v, float* f) {
    union { uint32_t u; __half2 h; } c;
    c.u = v.x; float2 t0 = __half22float2(c.h);
    c.u = v.y; float2 t1 = __half22float2(c.h);
    c.u = v.z; float2 t2 = __half22float2(c.h);
    c.u = v.w; float2 t3 = __half22float2(c.h);
    f[0] = t0.x; f[1] = t0.y; f[2] = t1.x; f[3] = t1.y;
    f[4] = t2.x; f[5] = t2.y; f[6] = t3.x; f[7] = t3.y;
}

// ============================================================================
// Convert kernels
// ============================================================================
__global__ void split_hi_kernel(const float* __restrict__ in,
                                __half* __restrict__ hi, int n4) {
    int i = blockIdx.x * blockDim.x + threadIdx.x;
    if (i >= n4) return;
    float4 v = ((const float4*)in)[i];
    ((__half2*)hi)[i * 2 + 0] = __halves2half2(__float2half_rn(v.x),
                                               __float2half_rn(v.y));
    ((__half2*)hi)[i * 2 + 1] = __halves2half2(__float2half_rn(v.z),
                                               __float2half_rn(v.w));
}

// in [R, C] fp32 -> out^T [C, R] half
__global__ void transpose_hi_kernel(const float* __restrict__ in,
                                    __half* __restrict__ hiT,
                                    int R, int C) {
    __shared__ float t[32][33];
    const int c0 = blockIdx.x * 32, r0 = blockIdx.y * 32;
    const int tx = threadIdx.x, ty = threadIdx.y;   // 32 x 8
    #pragma unroll
    for (int j = 0; j < 32; j += 8)
        t[ty + j][tx] = in[(size_t)(r0 + ty + j) * C + c0 + tx];
    __syncthreads();
    #pragma unroll
    for (int j = 0; j < 32; j += 8) {
        hiT[(size_t)(c0 + ty + j) * R + r0 + tx] = __float2half_rn(t[tx][ty + j]);
    }
}

// ============================================================================
// HMMA GEMM (1-term fp16): C[M,N] = A[M,K] @ W[K,N], W transposed [N,K].
// Block tile 256x128, BK=64 per stage, 16 warps (warp tile 64x32),
// 4-stage cp.async.  SMEM row layout (128B): [k0..31 | k32..63],
// 16B groups XOR (row&7).  Output fp16 (optionally bias+relu).
// ============================================================================
#define NST 4
#define A_BYTES 32768                    // 256 rows x 128B
#define STAGE_BYTES (A_BYTES + 16384)    // + B: 128 rows x 128B
#define GEMM_SMEM (NST * STAGE_BYTES)    // 192 KB

template <bool RELU_BIAS>
__global__ __launch_bounds__(512, 1)
void hmma_gemm(const __half* __restrict__ Ahi,
               const __half* __restrict__ Bhi,
               const float* __restrict__ bias,
               __half* __restrict__ outHi,
               int K)
{
    extern __shared__ __align__(1024) char smem[];
    const uint32_t smBase = smem_u32(smem);

    const int tid  = threadIdx.x;
    const int wid  = tid >> 5;
    const int lane = tid & 31;
    const int m0 = blockIdx.y * 256;
    const int n0 = blockIdx.x * 128;
    const int nk = K / 64;                    // BK=64 per stage

    const int wm = (wid & 3) * 64;
    const int wn = (wid >> 2) * 32;

    // --- loader mapping: half_sel selects k-offset (0 or 32) within row ---
    const int half_sel = tid & 1;
    const int arow = tid >> 1;                // 0..255
    const bool loadB = (tid < 256);
    const int brow = (tid >> 1) & 127;
    const __half* srcA = Ahi + (size_t)(m0 + arow) * K + half_sel * 32;
    const __half* srcB = Bhi + (size_t)(n0 + brow) * K + half_sel * 32;
    uint32_t dstA[4], dstB[4];
    #pragma unroll
    for (int g = 0; g < 4; g++) {
        const int lg = half_sel * 4 + g;
        dstA[g] = smBase + arow * 128 + ((lg ^ (arow & 7)) * 16);
        dstB[g] = smBase + A_BYTES + brow * 128 + ((lg ^ (brow & 7)) * 16);
    }

    auto load_stage = [&](int c, int s) {
        const uint32_t so = s * STAGE_BYTES;
        const __half* sa = srcA + c * 64;
        #pragma unroll
        for (int g = 0; g < 4; g++)
            cp_async16(dstA[g] + so, sa + g * 8);
        if (loadB) {
            const __half* sb = srcB + c * 64;
            #pragma unroll
            for (int g = 0; g < 4; g++)
                cp_async16(dstB[g] + so, sb + g * 8);
        }
    };

    float acc[4][4][4];
    #pragma unroll
    for (int mt = 0; mt < 4; mt++)
        #pragma unroll
        for (int nt = 0; nt < 4; nt++)
            #pragma unroll
            for (int j = 0; j < 4; j++)
                acc[mt][nt][j] = 0.f;

    #pragma unroll
    for (int c = 0; c < NST - 1; c++) {
        load_stage(c, c);
        CP_COMMIT();
    }

    const int arow_l = (lane & 15);
    const int agrp_l = (lane >> 4);
    const int brow_l = (lane & 7) + ((lane >> 4) << 3);
    const int bgrp_l = (lane >> 3) & 1;

    for (int c = 0; c < nk; c++) {
        CP_WAIT(NST - 2);
        __syncthreads();
        if (c + NST - 1 < nk)
            load_stage(c + NST - 1, (c + NST - 1) % NST);
        CP_COMMIT();

        const uint32_t aB = smBase + (c % NST) * STAGE_BYTES;
        const uint32_t bB = aB + A_BYTES;

        #pragma unroll
        for (int ks = 0; ks < 4; ks++) {           // 4 k-steps of 16
            const int agH = ks * 2 + agrp_l;       // groups 0..7
            const int bgH = ks * 2 + bgrp_l;

            uint32_t bf[2][4];
            #pragma unroll
            for (int np = 0; np < 2; np++) {
                const int row = wn + np * 16 + brow_l;
                ldsm_x4(bf[np], bB + row * 128 + ((bgH ^ (row & 7)) * 16));
            }

            #pragma unroll
            for (int mt = 0; mt < 4; mt++) {
                const int row = wm + mt * 16 + arow_l;
                uint32_t af[4];
                ldsm_x4(af, aB + row * 128 + ((agH ^ (row & 7)) * 16));
                #pragma unroll
                for (int nt = 0; nt < 4; nt++) {
                    const int np = nt >> 1, o = (nt & 1) * 2;
                    mma_f16(acc[mt][nt], af, bf[np][o], bf[np][o + 1]);
                }
            }
        }
    }

    // ---------------- epilogue: fp16 only ----------------
    const int r0 = lane >> 2;
    const int c0 = (lane & 3) * 2;

    float2 bias2[4];
    if (RELU_BIAS) {
        #pragma unroll
        for (int nt = 0; nt < 4; nt++) {
            const int gc = n0 + wn + nt * 8 + c0;
            bias2[nt].x = bias[gc];
            bias2[nt].y = bias[gc + 1];
        }
    }

    #pragma unroll
    for (int mt = 0; mt < 4; mt++) {
        #pragma unroll
        for (int h = 0; h < 2; h++) {
            const int row = m0 + wm + mt * 16 + h * 8 + r0;
            __half* op = outHi + (size_t)row * H_ + n0 + wn + c0;
            #pragma unroll
            for (int nt = 0; nt < 4; nt++) {
                float vx = acc[mt][nt][h * 2 + 0];
                float vy = acc[mt][nt][h * 2 + 1];
                if (RELU_BIAS) {
                    vx = fmaxf(vx + bias2[nt].x, 0.f);
                    vy = fmaxf(vy + bias2[nt].y, 0.f);
                }
                *(__half2*)(op + nt * 8) =
                    __halves2half2(__float2half_rn(vx), __float2half_rn(vy));
            }
        }
    }
}

// ============================================================================
// Local windowed attention — fp16 resident neighborhood (unchanged)
// ============================================================================
#define TS 16
#define HPH 1032   // row pitch in halves (2064 B)
#define ATT_SMEM (48 * HPH * 2 + TS * 36 * 4)

__global__ __launch_bounds__(256, 2)
void atten_kernel(const __half* __restrict__ hh, const __half* __restrict__ qh,
                  float* __restrict__ out)
{
    extern __shared__ __align__(16) char asmem[];
    __half* hs = (__half*)asmem;                       // [48][HPH]
    float (*sc)[36] = (float(*)[36])(asmem + 48 * HPH * 2);

    const int tid = threadIdx.x;
    const int b = blockIdx.y;
    const int s0 = blockIdx.x * TS;

    const __half* hB = hh + (size_t)b * S_ * H_;
    const __half* qB = qh + (size_t)b * S_ * H_;
    float*        oB = out + (size_t)b * S_ * H_;

    // ---- load 48 x 1024 fp16 neighborhood once ----
    for (int i = tid; i < 48 * 128; i += 256) {
        const int r = i >> 7;
        const int c = (i & 127) * 8;
        const int g = s0 - 16 + r;
        uint4 v = make_uint4(0, 0, 0, 0);
        if (g >= 0 && g < S_)
            v = *(const uint4*)(hB + (size_t)g * H_ + c);
        *(uint4*)&hs[r * HPH + c] = v;
    }
    __syncthreads();

    // ---------------- Phase A: scores ----------------
    const int warp = tid >> 5, lane = tid & 31;
    const int lane16 = lane & 15;
    const int sA = warp * 2 + (lane >> 4);   // 0..15
    const int kofs = lane16 * 8;

    float acc[AW];
    #pragma unroll
    for (int w = 0; w < AW; w++) acc[w] = 0.f;

    for (int kc = 0; kc < H_; kc += 128) {
        float qv[8];
        h8_to_f8(*(const uint4*)(qB + (size_t)(s0 + sA) * H_ + kc + kofs), qv);

        #pragma unroll
        for (int w = 0; w < AW; w++) {
            float hv[8];
            h8_to_f8(*(const uint4*)&hs[(sA + 32 - w) * HPH + kc + kofs], hv);
            float s = acc[w];
            #pragma unroll
            for (int k = 0; k < 8; k++) s += qv[k] * hv[k];
            acc[w] = s;
        }
    }

    #pragma unroll
    for (int w = 0; w < AW; w++) {
        #pragma unroll
        for (int d = 8; d >= 1; d >>= 1)
            acc[w] += __shfl_xor_sync(0xffffffffu, acc[w], d);
    }
    #pragma unroll
    for (int w = 0; w < AW; w++) {
        if ((w & 15) == lane16 && (w < 32 || lane16 == 0))
            sc[sA][w] = acc[w] * 0.03125f;   // 1/sqrt(1024)
    }
    __syncthreads();

    // ---------------- Phase B: softmax ----------------
    if (tid < TS) {
        float m = -1e30f;
        for (int w = 0; w < AW; w++) m = fmaxf(m, sc[tid][w]);
        float sum = 0.f;
        for (int w = 0; w < AW; w++) {
            const float e = expf(sc[tid][w] - m);
            sc[tid][w] = e;
            sum += e;
        }
        const float inv = 1.f / sum;
        for (int w = 0; w < AW; w++) sc[tid][w] *= inv;
    }
    __syncthreads();

    // ---------------- Phase C: weighted sum ----------------
    const int sg = ((tid >> 4) & 7) * 2;
    const int cg = (tid & 15) * 8;
    const int hsel = tid >> 7;

    for (int ci = 0; ci < 4; ci++) {
        const int kc = (hsel * 4 + ci) * 128;
        float a0[8], a1[8];
        #pragma unroll
        for (int k = 0; k < 8; k++) { a0[k] = 0.f; a1[k] = 0.f; }

        #pragma unroll
        for (int j = 0; j < 34; j++) {
            float hv[8];
            h8_to_f8(*(const uint4*)&hs[(sg + j) * HPH + kc + cg], hv);
            if (j <= 32) {
                const float p = sc[sg][32 - j];
                #pragma unroll
                for (int k = 0; k < 8; k++) a0[k] += p * hv[k];
            }
            if (j >= 1) {
                const float p = sc[sg + 1][33 - j];
                #pragma unroll
                for (int k = 0; k < 8; k++) a1[k] += p * hv[k];
            }
        }
        float* o0 = oB + (size_t)(s0 + sg) * H_ + kc + cg;
        float* o1 = oB + (size_t)(s0 + sg + 1) * H_ + kc + cg;
        *(float4*)(o0)     = make_float4(a0[0], a0[1], a0[2], a0[3]);
        *(float4*)(o0 + 4) = make_float4(a0[4], a0[5], a0[6], a0[7]);
        *(float4*)(o1)     = make_float4(a1[0], a1[1], a1[2], a1[3]);
        *(float4*)(o1 + 4) = make_float4(a1[4], a1[5], a1[6], a1[7]);
    }
}

// ============================================================================
// Launch
// ============================================================================
extern "C" void kernel_launch(void* const* d_in, const int* in_sizes, int n_in,
                              void* d_out, int out_size)
{
    const float* x  = (const float*)d_in[0];   // [4,2048,512]
    const float* W1 = (const float*)d_in[1];   // [512,1024]
    const float* b1 = (const float*)d_in[2];   // [1024]
    const float* Wq = (const float*)d_in[3];   // [1024,1024]
    float* out = (float*)d_out;                // [4,2048,1024]

    __half *xhi, *hhi, *qhi, *w1thi, *wqthi;
    cudaGetSymbolAddress((void**)&xhi, g_xhi);
    cudaGetSymbolAddress((void**)&hhi, g_hhi);
    cudaGetSymbolAddress((void**)&qhi, g_qhi);
    cudaGetSymbolAddress((void**)&w1thi, g_w1t_hi);
    cudaGetSymbolAddress((void**)&wqthi, g_wqt_hi);

    cudaFuncSetAttribute((const void*)hmma_gemm<true>,
                         cudaFuncAttributeMaxDynamicSharedMemorySize, GEMM_SMEM);
    cudaFuncSetAttribute((const void*)hmma_gemm<false>,
                         cudaFuncAttributeMaxDynamicSharedMemorySize, GEMM_SMEM);
    cudaFuncSetAttribute((const void*)atten_kernel,
                         cudaFuncAttributeMaxDynamicSharedMemorySize, ATT_SMEM);

    // Converts
    {
        int n4 = M_ * IN_ / 4;
        split_hi_kernel<<<(n4 + 255) / 256, 256>>>(x, xhi, n4);
        dim3 t(32, 8);
        transpose_hi_kernel<<<dim3(H_ / 32, IN_ / 32), t>>>(W1, w1thi, IN_, H_);
        transpose_hi_kernel<<<dim3(H_ / 32, H_ / 32), t>>>(Wq, wqthi, H_, H_);
    }

    // GEMM1: hhi = fp16(relu(xhi @ W1hi + b1))   (1-term)
    {
        dim3 grid(H_ / 128, M_ / 256);
        hmma_gemm<true><<<grid, 512, GEMM_SMEM>>>(xhi, w1thi, b1, hhi, IN_);
    }
    // GEMM2: qhi = fp16(hhi @ Wqhi)   (1-term)
    {
        dim3 grid(H_ / 128, M_ / 256);
        hmma_gemm<false><<<grid, 512, GEMM_SMEM>>>(hhi, wqthi, nullptr, qhi, H_);
    }
    // Attention
    {
        dim3 grid(S_ / TS, B_);
        atten_kernel<<<grid, 256, ATT_SMEM>>>(hhi, qhi, out);
    }
}